// round 3
// baseline (speedup 1.0000x reference)
#include <cuda_runtime.h>

#define B_   2
#define S_   2048
#define D_   768
#define H_   12
#define DH_  64
#define QKVLD (3 * D_)   // 2304

// Scratch (allocation-free rule: __device__ globals)
__device__ float g_qkv[(size_t)B_ * S_ * 3 * D_];   // [B*S, 3D]
__device__ float g_att[(size_t)B_ * S_ * D_];       // [B*S, D]

// ---------------------------------------------------------------------------
// Packed fp32x2 helpers (sm_103a: fma pipe is f32x2-wide; scalar FFMA fills
// only half of it. fma.rn.f32x2 is bit-exact per lane vs scalar fma.rn.)
// ---------------------------------------------------------------------------
__device__ __forceinline__ void ffma2(unsigned long long& d,
                                      unsigned long long a,
                                      unsigned long long b) {
    asm("fma.rn.f32x2 %0, %1, %2, %0;" : "+l"(d) : "l"(a), "l"(b));
}
__device__ __forceinline__ void mul2(unsigned long long& d, unsigned long long a) {
    asm("mul.rn.f32x2 %0, %0, %1;" : "+l"(d) : "l"(a));
}
__device__ __forceinline__ float2 upk(unsigned long long v) {
    float2 r; asm("mov.b64 {%0, %1}, %2;" : "=f"(r.x), "=f"(r.y) : "l"(v)); return r;
}
__device__ __forceinline__ unsigned long long pk2(float x, float y) {
    unsigned long long r; asm("mov.b64 %0, {%1, %2};" : "=l"(r) : "f"(x), "f"(y)); return r;
}

// ---------------------------------------------------------------------------
// Tiled SGEMM with bias, f32x2 math: C[M,N] = A[M,K] @ Bm[K,N] + bias[N]
// BM=BN=128, BK=8, 256 threads, 8x8 per thread (2x2 quadrants of 4x4).
// A stored transposed AND duplicated in smem (As_dup[k][2*row{+0,1}] = a):
// compute loads of A depend only on ty -> warp-broadcast, conflict-free.
// B pairs are naturally consecutive floats. AD=268 makes dup stores
// conflict-free across the two k-row groups.
// ---------------------------------------------------------------------------
#define AD 268
__global__ __launch_bounds__(256, 2) void sgemm_bias(
    const float* __restrict__ A, const float* __restrict__ Bm,
    const float* __restrict__ bias, float* __restrict__ C,
    int M, int N, int K)
{
    __shared__ float Ad[8 * AD];     // duplicated transposed A tile
    __shared__ float Bs[8][132];

    const int tid  = threadIdx.x;
    const int tx   = tid & 15;
    const int ty   = tid >> 4;
    const int brow = blockIdx.y << 7;
    const int bcol = blockIdx.x << 7;

    const int aRow = tid >> 1;         // 0..127
    const int aCol = (tid & 1) << 2;   // 0 or 4
    const int bRow = tid >> 5;         // 0..7
    const int bCol = (tid & 31) << 2;  // 0..124

    const float* Ap = A  + (size_t)(brow + aRow) * K + aCol;
    const float* Bp = Bm + (size_t)bRow * N + bcol + bCol;

    unsigned long long acc[2][2][4][2] = {};  // [p][q][i][j2] packed j-pairs

    float4 av = *(const float4*)(Ap);
    float4 bv = *(const float4*)(Bp);

    for (int k0 = 0; k0 < K; k0 += 8) {
        // A: transposed duplicated stores (STS.64 of {v,v})
        *(float2*)&Ad[(aCol + 0) * AD + 2 * aRow] = make_float2(av.x, av.x);
        *(float2*)&Ad[(aCol + 1) * AD + 2 * aRow] = make_float2(av.y, av.y);
        *(float2*)&Ad[(aCol + 2) * AD + 2 * aRow] = make_float2(av.z, av.z);
        *(float2*)&Ad[(aCol + 3) * AD + 2 * aRow] = make_float2(av.w, av.w);
        *(float4*)&Bs[bRow][bCol] = bv;
        __syncthreads();

        float4 avn = av, bvn = bv;
        if (k0 + 8 < K) {  // register prefetch of next tile
            avn = *(const float4*)(Ap + k0 + 8);
            bvn = *(const float4*)(Bp + (size_t)(k0 + 8) * N);
        }

#pragma unroll
        for (int k = 0; k < 8; k++) {
            const float* ar = Ad + k * AD;
            // broadcast loads: dup pairs for rows 4ty..4ty+3 (p=0), +64 (p=1)
            ulonglong2 a0 = *(const ulonglong2*)&ar[8 * ty];            // i=0,1
            ulonglong2 a1 = *(const ulonglong2*)&ar[8 * ty + 4];        // i=2,3
            ulonglong2 a2 = *(const ulonglong2*)&ar[128 + 8 * ty];      // p=1 i=0,1
            ulonglong2 a3 = *(const ulonglong2*)&ar[128 + 8 * ty + 4];  // p=1 i=2,3
            ulonglong2 b0 = *(const ulonglong2*)&Bs[k][tx << 2];        // q=0 pairs
            ulonglong2 b1 = *(const ulonglong2*)&Bs[k][(tx << 2) + 64]; // q=1 pairs

            ffma2(acc[0][0][0][0], a0.x, b0.x); ffma2(acc[0][0][0][1], a0.x, b0.y);
            ffma2(acc[0][1][0][0], a0.x, b1.x); ffma2(acc[0][1][0][1], a0.x, b1.y);
            ffma2(acc[0][0][1][0], a0.y, b0.x); ffma2(acc[0][0][1][1], a0.y, b0.y);
            ffma2(acc[0][1][1][0], a0.y, b1.x); ffma2(acc[0][1][1][1], a0.y, b1.y);
            ffma2(acc[0][0][2][0], a1.x, b0.x); ffma2(acc[0][0][2][1], a1.x, b0.y);
            ffma2(acc[0][1][2][0], a1.x, b1.x); ffma2(acc[0][1][2][1], a1.x, b1.y);
            ffma2(acc[0][0][3][0], a1.y, b0.x); ffma2(acc[0][0][3][1], a1.y, b0.y);
            ffma2(acc[0][1][3][0], a1.y, b1.x); ffma2(acc[0][1][3][1], a1.y, b1.y);

            ffma2(acc[1][0][0][0], a2.x, b0.x); ffma2(acc[1][0][0][1], a2.x, b0.y);
            ffma2(acc[1][1][0][0], a2.x, b1.x); ffma2(acc[1][1][0][1], a2.x, b1.y);
            ffma2(acc[1][0][1][0], a2.y, b0.x); ffma2(acc[1][0][1][1], a2.y, b0.y);
            ffma2(acc[1][1][1][0], a2.y, b1.x); ffma2(acc[1][1][1][1], a2.y, b1.y);
            ffma2(acc[1][0][2][0], a3.x, b0.x); ffma2(acc[1][0][2][1], a3.x, b0.y);
            ffma2(acc[1][1][2][0], a3.x, b1.x); ffma2(acc[1][1][2][1], a3.x, b1.y);
            ffma2(acc[1][0][3][0], a3.y, b0.x); ffma2(acc[1][0][3][1], a3.y, b0.y);
            ffma2(acc[1][1][3][0], a3.y, b1.x); ffma2(acc[1][1][3][1], a3.y, b1.y);
        }
        __syncthreads();
        av = avn; bv = bvn;
    }

#pragma unroll
    for (int p = 0; p < 2; p++)
#pragma unroll
        for (int i = 0; i < 4; i++) {
            int row = brow + (p << 6) + (ty << 2) + i;
#pragma unroll
            for (int q = 0; q < 2; q++) {
                int col = bcol + (q << 6) + (tx << 2);
                float2 u0 = upk(acc[p][q][i][0]);
                float2 u1 = upk(acc[p][q][i][1]);
                float4 o;
                o.x = u0.x + bias[col + 0];
                o.y = u0.y + bias[col + 1];
                o.z = u1.x + bias[col + 2];
                o.w = u1.y + bias[col + 3];
                *(float4*)&C[(size_t)row * N + col] = o;
            }
        }
}

// ---------------------------------------------------------------------------
// Flash attention, fp32, causal. BM=BN=64, DH=64, 256 threads, f32x2 math.
// j (tx) dimension packed in pairs: K and V supply natural consecutive pairs.
// Q and P (ty-indexed operands) are stored DUPLICATED in smem so their packed
// operands load via warp-broadcast (conflict-free). Q/P dup tiles use an
// XOR-group swizzle (group ^= (row>>2)&7) to keep the dup stores ~2-way.
// ---------------------------------------------------------------------------
__device__ __forceinline__ int trn_idx(int d, int c) {
    // transposed tile [d][c], 64 floats/row, group-swizzled by (d>>2)
    return (d << 6) + ((((c >> 2) ^ (d >> 2)) & 15) << 2) + (c & 3);
}

#define QD 132   // row stride of dup tiles (floats)

__global__ __launch_bounds__(256, 2) void flash_attn(
    const float* __restrict__ qkv, float* __restrict__ out)
{
    extern __shared__ float sm[];
    float* Qd = sm;              // [64][132] dup'd transposed Q (rows=d)
    float* Ks = sm + 8448;       // [64][64]  transposed swizzled K
    float* Vs = sm + 12544;      // [64][64]  natural V [c][d]
    float* Pd = sm + 16640;      // [64][132] dup'd transposed P (rows=c)
    // total floats = 25088 -> 100352 bytes

    const int tid  = threadIdx.x;
    const int tx   = tid & 15;
    const int ty   = tid >> 4;
    const int mblk = (int)gridDim.x - 1 - (int)blockIdx.x;  // heavy blocks first
    const int h    = blockIdx.y;
    const int b    = blockIdx.z;
    const int m0   = mblk << 6;

    const float* Qg = qkv + (size_t)b * S_ * QKVLD + h * DH_;
    const float* Kg = Qg + D_;
    const float* Vg = Qg + 2 * D_;

    // Load Q tile transposed + duplicated + group-swizzled
#pragma unroll
    for (int l = 0; l < 4; l++) {
        int f4 = (l << 8) + tid;
        int r  = f4 >> 4;
        int d0 = (f4 & 15) << 2;
        float4 v = *(const float4*)&Qg[(size_t)(m0 + r) * QKVLD + d0];
        float vv[4] = {v.x, v.y, v.z, v.w};
        int rh = r >> 1;
        int rb = (r & 1) << 1;
#pragma unroll
        for (int kk = 0; kk < 4; kk++) {
            int d = d0 + kk;
            int g = rh ^ ((d >> 2) & 7);
            *(float2*)&Qd[d * QD + (g << 2) + rb] = make_float2(vv[kk], vv[kk]);
        }
    }

    float m_i[4], l_i[4];
    unsigned long long o2[4][2] = {};   // packed j-pairs
#pragma unroll
    for (int i = 0; i < 4; i++) { m_i[i] = -1e30f; l_i[i] = 0.f; }

    for (int nb = 0; nb <= mblk; nb++) {
        const int n0 = nb << 6;
        __syncthreads();  // prior reads of Ks/Vs/Pd done

        // Load K (transposed swizzled) and V (natural)
#pragma unroll
        for (int l = 0; l < 4; l++) {
            int f4 = (l << 8) + tid;
            int c  = f4 >> 4;
            int d0 = (f4 & 15) << 2;
            float4 kv = *(const float4*)&Kg[(size_t)(n0 + c) * QKVLD + d0];
            Ks[trn_idx(d0 + 0, c)] = kv.x;
            Ks[trn_idx(d0 + 1, c)] = kv.y;
            Ks[trn_idx(d0 + 2, c)] = kv.z;
            Ks[trn_idx(d0 + 3, c)] = kv.w;
            float4 vv = *(const float4*)&Vg[(size_t)(n0 + c) * QKVLD + d0];
            *(float4*)&Vs[(c << 6) + d0] = vv;
        }
        __syncthreads();

        // Scores: S = Q K^T, packed over j. a = dup q (broadcast), b = k pairs.
        unsigned long long s2[4][2] = {};
#pragma unroll 8
        for (int d = 0; d < 64; d++) {
            int sw = (d >> 2) & 7;
            const float* qrow = Qd + d * QD;
            ulonglong2 aA = *(const ulonglong2*)&qrow[(((2 * ty) ^ sw)) << 2];      // i=0,1
            ulonglong2 aB = *(const ulonglong2*)&qrow[(((2 * ty + 1) ^ sw)) << 2];  // i=2,3
            ulonglong2 bb = *(const ulonglong2*)&Ks[(d << 6) + (((tx ^ (d >> 2)) & 15) << 2)];
            ffma2(s2[0][0], aA.x, bb.x); ffma2(s2[0][1], aA.x, bb.y);
            ffma2(s2[1][0], aA.y, bb.x); ffma2(s2[1][1], aA.y, bb.y);
            ffma2(s2[2][0], aB.x, bb.x); ffma2(s2[2][1], aB.x, bb.y);
            ffma2(s2[3][0], aB.y, bb.x); ffma2(s2[3][1], aB.y, bb.y);
        }

        // Unpack, scale + causal mask
        float s[4][4];
#pragma unroll
        for (int i = 0; i < 4; i++) {
            float2 u0 = upk(s2[i][0]);
            float2 u1 = upk(s2[i][1]);
            s[i][0] = u0.x; s[i][1] = u0.y; s[i][2] = u1.x; s[i][3] = u1.y;
        }
        const float scale = 0.125f;
        if (nb == mblk) {
#pragma unroll
            for (int i = 0; i < 4; i++)
#pragma unroll
                for (int j = 0; j < 4; j++) {
                    int rloc = (ty << 2) + i, cloc = (tx << 2) + j;
                    s[i][j] = (cloc > rloc) ? -1e30f : s[i][j] * scale;
                }
        } else {
#pragma unroll
            for (int i = 0; i < 4; i++)
#pragma unroll
                for (int j = 0; j < 4; j++) s[i][j] *= scale;
        }

        // Online softmax + duplicated P store
#pragma unroll
        for (int i = 0; i < 4; i++) {
            float mx = fmaxf(fmaxf(s[i][0], s[i][1]), fmaxf(s[i][2], s[i][3]));
#pragma unroll
            for (int off = 8; off > 0; off >>= 1)
                mx = fmaxf(mx, __shfl_xor_sync(0xffffffffu, mx, off));
            float mnew  = fmaxf(m_i[i], mx);
            float alpha = __expf(m_i[i] - mnew);
            float p0 = __expf(s[i][0] - mnew);
            float p1 = __expf(s[i][1] - mnew);
            float p2 = __expf(s[i][2] - mnew);
            float p3 = __expf(s[i][3] - mnew);
            float rs = (p0 + p1) + (p2 + p3);
#pragma unroll
            for (int off = 8; off > 0; off >>= 1)
                rs += __shfl_xor_sync(0xffffffffu, rs, off);
            l_i[i] = l_i[i] * alpha + rs;
            m_i[i] = mnew;
            unsigned long long ap = pk2(alpha, alpha);
            mul2(o2[i][0], ap);
            mul2(o2[i][1], ap);
            // store duplicated P: row c = 4tx+j, col pair 2r (r = 4ty+i), swizzled
            int rh = ((ty << 2) + i) >> 1;        // 2ty + (i>>1)
            int rb = (i & 1) << 1;
            int g  = rh ^ (tx & 7);               // (c>>2)&7 == tx&7 for c=4tx+j
            float* pb = Pd + ((tx << 2) * QD) + (g << 2) + rb;
            *(float2*)&pb[0 * QD] = make_float2(p0, p0);
            *(float2*)&pb[1 * QD] = make_float2(p1, p1);
            *(float2*)&pb[2 * QD] = make_float2(p2, p2);
            *(float2*)&pb[3 * QD] = make_float2(p3, p3);
        }
        __syncthreads();

        // O += P @ V, packed over j. a = dup p (broadcast), b = v pairs.
#pragma unroll 8
        for (int c = 0; c < 64; c++) {
            int sw = (c >> 2) & 7;
            const float* prow = Pd + c * QD;
            ulonglong2 aA = *(const ulonglong2*)&prow[(((2 * ty) ^ sw)) << 2];      // i=0,1
            ulonglong2 aB = *(const ulonglong2*)&prow[(((2 * ty + 1) ^ sw)) << 2];  // i=2,3
            ulonglong2 bb = *(const ulonglong2*)&Vs[(c << 6) + (tx << 2)];
            ffma2(o2[0][0], aA.x, bb.x); ffma2(o2[0][1], aA.x, bb.y);
            ffma2(o2[1][0], aA.y, bb.x); ffma2(o2[1][1], aA.y, bb.y);
            ffma2(o2[2][0], aB.x, bb.x); ffma2(o2[2][1], aB.x, bb.y);
            ffma2(o2[3][0], aB.y, bb.x); ffma2(o2[3][1], aB.y, bb.y);
        }
    }

    // Epilogue: normalize and write merged-head layout [B*S, D]
#pragma unroll
    for (int i = 0; i < 4; i++) {
        float inv = 1.0f / l_i[i];
        float2 u0 = upk(o2[i][0]);
        float2 u1 = upk(o2[i][1]);
        float4 ov;
        ov.x = u0.x * inv;
        ov.y = u0.y * inv;
        ov.z = u1.x * inv;
        ov.w = u1.y * inv;
        size_t row = (size_t)b * S_ + m0 + (ty << 2) + i;
        *(float4*)&out[row * D_ + h * DH_ + (tx << 2)] = ov;
    }
}

// ---------------------------------------------------------------------------
extern "C" void kernel_launch(void* const* d_in, const int* in_sizes, int n_in,
                              void* d_out, int out_size)
{
    (void)in_sizes; (void)n_in; (void)out_size;
    const float* x    = (const float*)d_in[0];
    // d_in[1] = attn_mask (static causal; encoded directly in the kernel)
    const float* Wqkv = (const float*)d_in[2];
    const float* bqkv = (const float*)d_in[3];
    const float* Wp   = (const float*)d_in[4];
    const float* bp   = (const float*)d_in[5];
    float* out = (float*)d_out;

    float* qkv = nullptr;
    float* att = nullptr;
    cudaGetSymbolAddress((void**)&qkv, g_qkv);
    cudaGetSymbolAddress((void**)&att, g_att);

    cudaFuncSetAttribute(flash_attn,
                         cudaFuncAttributeMaxDynamicSharedMemorySize, 100352);

    const int M = B_ * S_;  // 4096

    // QKV projection: [4096,768] @ [768,2304] + b
    sgemm_bias<<<dim3(QKVLD / 128, M / 128), 256>>>(x, Wqkv, bqkv, qkv, M, QKVLD, D_);

    // Causal flash attention -> merged heads [4096, 768]
    flash_attn<<<dim3(S_ / 64, H_, B_), 256, 100352>>>(qkv, att);

    // Output projection: [4096,768] @ [768,768] + b
    sgemm_bias<<<dim3(D_ / 128, M / 128), 256>>>(att, Wp, bp, out, M, D_, D_);
}

// round 5
// speedup vs baseline: 2.1929x; 2.1929x over previous
#include <cuda_runtime.h>
#include <cuda_bf16.h>
#include <cstdint>

#define B_   2
#define S_   2048
#define D_   768
#define H_   12
#define DH_  64
#define QKVLD (3 * D_)   // 2304
#define M_TOT (B_ * S_)  // 4096

// ---------------------------------------------------------------------------
// Scratch (allocation-free rule: __device__ globals)
// ---------------------------------------------------------------------------
__device__ float g_qkv[(size_t)M_TOT * QKVLD];           // [B*S, 3D]
__device__ float g_att[(size_t)M_TOT * D_];              // [B*S, D]
__device__ __nv_bfloat16 g_wqkvT_hi[(size_t)QKVLD * D_]; // W_qkv^T [2304,768]
__device__ __nv_bfloat16 g_wqkvT_lo[(size_t)QKVLD * D_];
__device__ __nv_bfloat16 g_wpT_hi[(size_t)D_ * D_];      // W_proj^T [768,768]
__device__ __nv_bfloat16 g_wpT_lo[(size_t)D_ * D_];

// ---------------------------------------------------------------------------
// sm_80-level building blocks (compile clean for compute_103)
// ---------------------------------------------------------------------------
__device__ __forceinline__ uint32_t smem_u32(const void* p) {
    uint32_t a;
    asm("{ .reg .u64 t; cvta.to.shared.u64 t, %1; cvt.u32.u64 %0, t; }" : "=r"(a) : "l"(p));
    return a;
}
__device__ __forceinline__ void cp_async16(uint32_t dst, const void* src) {
    asm volatile("cp.async.cg.shared.global [%0], [%1], 16;" :: "r"(dst), "l"(src));
}
__device__ __forceinline__ void cp_commit() { asm volatile("cp.async.commit_group;"); }
__device__ __forceinline__ void cp_wait0()  { asm volatile("cp.async.wait_group 0;"); }

__device__ __forceinline__ void ldm4(uint32_t* r, uint32_t addr) {
    asm volatile("ldmatrix.sync.aligned.m8n8.x4.shared.b16 {%0,%1,%2,%3}, [%4];"
        : "=r"(r[0]), "=r"(r[1]), "=r"(r[2]), "=r"(r[3]) : "r"(addr));
}
__device__ __forceinline__ void ldm2(uint32_t* r, uint32_t addr) {
    asm volatile("ldmatrix.sync.aligned.m8n8.x2.shared.b16 {%0,%1}, [%2];"
        : "=r"(r[0]), "=r"(r[1]) : "r"(addr));
}
__device__ __forceinline__ void mma16816(float* d, const uint32_t* a, const uint32_t* b) {
    asm volatile(
        "mma.sync.aligned.m16n8k16.row.col.f32.bf16.bf16.f32 "
        "{%0,%1,%2,%3}, {%4,%5,%6,%7}, {%8,%9}, {%0,%1,%2,%3};"
        : "+f"(d[0]), "+f"(d[1]), "+f"(d[2]), "+f"(d[3])
        : "r"(a[0]), "r"(a[1]), "r"(a[2]), "r"(a[3]), "r"(b[0]), "r"(b[1]));
}
__device__ __forceinline__ uint32_t pack_bf2(float a, float b) {
    __nv_bfloat162 t = __floats2bfloat162_rn(a, b);
    return *reinterpret_cast<uint32_t*>(&t);
}

// ---------------------------------------------------------------------------
// Weight transpose + bf16 hi/lo split: W[K,N] -> T{hi,lo}[N,K]
// ---------------------------------------------------------------------------
__global__ void wtrans(const float* __restrict__ W,
                       __nv_bfloat16* __restrict__ Thi,
                       __nv_bfloat16* __restrict__ Tlo, int K, int N)
{
    __shared__ float t[32][33];
    int bx = blockIdx.x << 5;   // n
    int by = blockIdx.y << 5;   // k
    int tx = threadIdx.x, ty = threadIdx.y;
#pragma unroll
    for (int j = 0; j < 4; j++)
        t[ty + j * 8][tx] = W[(size_t)(by + ty + j * 8) * N + bx + tx];
    __syncthreads();
#pragma unroll
    for (int j = 0; j < 4; j++) {
        float v = t[tx][ty + j * 8];
        __nv_bfloat16 hi = __float2bfloat16(v);
        float lo = v - __bfloat162float(hi);
        size_t o = (size_t)(bx + ty + j * 8) * K + by + tx;
        Thi[o] = hi;
        Tlo[o] = __float2bfloat16(lo);
    }
}

// ---------------------------------------------------------------------------
// bf16x3 tensor-core GEMM (mma.sync): C[M,Ntot] = A[M,K] @ Bt[Ntot,K]^T + bias
// CTA 128x128, BK=64 bf16 (128B rows, SW128 XOR-chunk swizzle).
// 8 warps: 2(m) x 4(n), warp tile 64x32 -> 4 m16-tiles x 4 n8-tiles.
// A fp32 split to hi/lo on the fly; B hi/lo pre-split, fetched via cp.async.
// Products: Ahi*Bhi + Alo*Bhi + Ahi*Blo  (lo*lo dropped, ~2^-16 rel).
// ---------------------------------------------------------------------------
#define SWZOFF(r, g) (((uint32_t)(r) << 7) + (((uint32_t)((g) ^ ((r) & 7))) << 4))

__global__ __launch_bounds__(256) void gemm_mma(
    const float* __restrict__ A,
    const __nv_bfloat16* __restrict__ Bthi,
    const __nv_bfloat16* __restrict__ Btlo,
    const float* __restrict__ bias, float* __restrict__ C,
    int M, int Ntot, int K)
{
    extern __shared__ __align__(1024) uint8_t smem[];
    const uint32_t sb  = smem_u32(smem);
    const uint32_t Ahi = sb, Alo = sb + 16384, Bhi = sb + 32768, Blo = sb + 49152;

    const int tid  = threadIdx.x;
    const int lane = tid & 31;
    const int wid  = tid >> 5;
    const int wm   = wid & 1;          // m half (64 rows)
    const int wn   = wid >> 1;         // n quarter (32 cols)
    const int m0   = blockIdx.y << 7;
    const int n0   = blockIdx.x << 7;

    float acc[4][4][4];
#pragma unroll
    for (int mt = 0; mt < 4; mt++)
#pragma unroll
        for (int nt = 0; nt < 4; nt++)
#pragma unroll
            for (int e = 0; e < 4; e++) acc[mt][nt][e] = 0.f;

    // ldmatrix source addresses (depend only on lane)
    const int aRow = lane & 15;               // row within m16 tile
    const int aKs  = lane >> 4;               // 0/1 -> k chunk select
    const int bRow = lane & 7;                // row within n8 tile
    const int bKs  = (lane >> 3) & 1;

    const int nchunks = K >> 6;
    for (int c = 0; c < nchunks; c++) {
        const int k0 = c << 6;
        __syncthreads();

        // ---- B hi/lo via cp.async (16B per chunk) ----
#pragma unroll
        for (int u = 0; u < 4; u++) {
            int unit = tid + (u << 8);
            int r = unit >> 3, g = unit & 7;
            uint32_t off = SWZOFF(r, g);
            const __nv_bfloat16* sh = Bthi + (size_t)(n0 + r) * K + k0 + (g << 3);
            const __nv_bfloat16* sl = Btlo + (size_t)(n0 + r) * K + k0 + (g << 3);
            cp_async16(Bhi + off, sh);
            cp_async16(Blo + off, sl);
        }
        cp_commit();

        // ---- A fp32 -> bf16 hi/lo, swizzled stores ----
#pragma unroll
        for (int u = 0; u < 4; u++) {
            int unit = tid + (u << 8);
            int r = unit >> 3, g = unit & 7;
            const float* ap = A + (size_t)(m0 + r) * K + k0 + (g << 3);
            float4 v0 = *(const float4*)ap;
            float4 v1 = *(const float4*)(ap + 4);
            float f[8] = {v0.x, v0.y, v0.z, v0.w, v1.x, v1.y, v1.z, v1.w};
            float l[8];
#pragma unroll
            for (int e = 0; e < 8; e++) {
                __nv_bfloat16 h = __float2bfloat16(f[e]);
                l[e] = f[e] - __bfloat162float(h);
            }
            uint4 hp, lp;
            hp.x = pack_bf2(f[0], f[1]); hp.y = pack_bf2(f[2], f[3]);
            hp.z = pack_bf2(f[4], f[5]); hp.w = pack_bf2(f[6], f[7]);
            lp.x = pack_bf2(l[0], l[1]); lp.y = pack_bf2(l[2], l[3]);
            lp.z = pack_bf2(l[4], l[5]); lp.w = pack_bf2(l[6], l[7]);
            uint32_t off = SWZOFF(r, g);
            *(uint4*)(smem + off)           = hp;   // Ahi
            *(uint4*)(smem + 16384 + off)   = lp;   // Alo
        }
        cp_wait0();
        __syncthreads();

        // ---- 4 k16 steps ----
#pragma unroll
        for (int ks = 0; ks < 4; ks++) {
            const int kc = ks << 1;   // 16B-chunk index of this k16 step
            uint32_t ah[4][4], al[4][4];
#pragma unroll
            for (int mt = 0; mt < 4; mt++) {
                int row = (wm << 6) + (mt << 4) + aRow;
                uint32_t off = SWZOFF(row, kc + aKs);
                ldm4(ah[mt], Ahi + off);
                ldm4(al[mt], Alo + off);
            }
            uint32_t bh[4][2], bl[4][2];
#pragma unroll
            for (int nt = 0; nt < 4; nt++) {
                int row = (wn << 5) + (nt << 3) + bRow;
                uint32_t off = SWZOFF(row, kc + bKs);
                ldm2(bh[nt], Bhi + off);
                ldm2(bl[nt], Blo + off);
            }
#pragma unroll
            for (int mt = 0; mt < 4; mt++)
#pragma unroll
                for (int nt = 0; nt < 4; nt++) {
                    mma16816(acc[mt][nt], ah[mt], bh[nt]);
                    mma16816(acc[mt][nt], al[mt], bh[nt]);
                    mma16816(acc[mt][nt], ah[mt], bl[nt]);
                }
        }
    }

    // ---- epilogue: add bias, store fp32 ----
#pragma unroll
    for (int mt = 0; mt < 4; mt++) {
        int row = m0 + (wm << 6) + (mt << 4) + (lane >> 2);
#pragma unroll
        for (int nt = 0; nt < 4; nt++) {
            int col = n0 + (wn << 5) + (nt << 3) + ((lane & 3) << 1);
            float2 bv = *(const float2*)&bias[col];
            float2 o0, o1;
            o0.x = acc[mt][nt][0] + bv.x;
            o0.y = acc[mt][nt][1] + bv.y;
            o1.x = acc[mt][nt][2] + bv.x;
            o1.y = acc[mt][nt][3] + bv.y;
            *(float2*)&C[(size_t)row * Ntot + col]       = o0;
            *(float2*)&C[(size_t)(row + 8) * Ntot + col] = o1;
        }
    }
}

// ---------------------------------------------------------------------------
// Flash attention, fp32, causal (Round-2 scalar version, known good).
// ---------------------------------------------------------------------------
__device__ __forceinline__ int trn_idx(int d, int c) {
    return (d << 6) + ((((c >> 2) ^ (d >> 2)) & 15) << 2) + (c & 3);
}

__global__ __launch_bounds__(256) void flash_attn(
    const float* __restrict__ qkv, float* __restrict__ out)
{
    extern __shared__ float sm[];
    float* Qs = sm;
    float* Ks = sm + 4096;
    float* Vs = sm + 8192;
    float* Ps = sm + 12288;

    const int tid  = threadIdx.x;
    const int tx   = tid & 15;
    const int ty   = tid >> 4;
    const int mblk = (int)gridDim.x - 1 - (int)blockIdx.x;
    const int h    = blockIdx.y;
    const int b    = blockIdx.z;
    const int m0   = mblk << 6;

    const float* Qg = qkv + (size_t)b * S_ * QKVLD + h * DH_;
    const float* Kg = Qg + D_;
    const float* Vg = Qg + 2 * D_;

#pragma unroll
    for (int l = 0; l < 4; l++) {
        int f4 = (l << 8) + tid;
        int r  = f4 >> 4;
        int d0 = (f4 & 15) << 2;
        float4 v = *(const float4*)&Qg[(size_t)(m0 + r) * QKVLD + d0];
        Qs[trn_idx(d0 + 0, r)] = v.x;
        Qs[trn_idx(d0 + 1, r)] = v.y;
        Qs[trn_idx(d0 + 2, r)] = v.z;
        Qs[trn_idx(d0 + 3, r)] = v.w;
    }

    float m_i[4], l_i[4], o[4][4];
#pragma unroll
    for (int i = 0; i < 4; i++) {
        m_i[i] = -1e30f;
        l_i[i] = 0.f;
#pragma unroll
        for (int j = 0; j < 4; j++) o[i][j] = 0.f;
    }

    for (int nb = 0; nb <= mblk; nb++) {
        const int n0 = nb << 6;
        __syncthreads();

#pragma unroll
        for (int l = 0; l < 4; l++) {
            int f4 = (l << 8) + tid;
            int c  = f4 >> 4;
            int d0 = (f4 & 15) << 2;
            float4 kv = *(const float4*)&Kg[(size_t)(n0 + c) * QKVLD + d0];
            Ks[trn_idx(d0 + 0, c)] = kv.x;
            Ks[trn_idx(d0 + 1, c)] = kv.y;
            Ks[trn_idx(d0 + 2, c)] = kv.z;
            Ks[trn_idx(d0 + 3, c)] = kv.w;
            float4 vv = *(const float4*)&Vg[(size_t)(n0 + c) * QKVLD + d0];
            *(float4*)&Vs[(c << 6) + d0] = vv;
        }
        __syncthreads();

        float s[4][4];
#pragma unroll
        for (int i = 0; i < 4; i++)
#pragma unroll
            for (int j = 0; j < 4; j++) s[i][j] = 0.f;

#pragma unroll 16
        for (int d = 0; d < 64; d++) {
            float4 a  = *(const float4*)&Qs[(d << 6) + (((ty ^ (d >> 2)) & 15) << 2)];
            float4 bb = *(const float4*)&Ks[(d << 6) + (((tx ^ (d >> 2)) & 15) << 2)];
            float avv[4] = {a.x, a.y, a.z, a.w};
            float bvv[4] = {bb.x, bb.y, bb.z, bb.w};
#pragma unroll
            for (int i = 0; i < 4; i++)
#pragma unroll
                for (int j = 0; j < 4; j++)
                    s[i][j] += avv[i] * bvv[j];
        }

        const float scale = 0.125f;
        if (nb == mblk) {
#pragma unroll
            for (int i = 0; i < 4; i++)
#pragma unroll
                for (int j = 0; j < 4; j++) {
                    int rloc = (ty << 2) + i, cloc = (tx << 2) + j;
                    s[i][j] = (cloc > rloc) ? -1e30f : s[i][j] * scale;
                }
        } else {
#pragma unroll
            for (int i = 0; i < 4; i++)
#pragma unroll
                for (int j = 0; j < 4; j++) s[i][j] *= scale;
        }

#pragma unroll
        for (int i = 0; i < 4; i++) {
            float mx = fmaxf(fmaxf(s[i][0], s[i][1]), fmaxf(s[i][2], s[i][3]));
#pragma unroll
            for (int off = 8; off > 0; off >>= 1)
                mx = fmaxf(mx, __shfl_xor_sync(0xffffffffu, mx, off));
            float mnew  = fmaxf(m_i[i], mx);
            float alpha = __expf(m_i[i] - mnew);
            float p0 = __expf(s[i][0] - mnew);
            float p1 = __expf(s[i][1] - mnew);
            float p2 = __expf(s[i][2] - mnew);
            float p3 = __expf(s[i][3] - mnew);
            float rs = (p0 + p1) + (p2 + p3);
#pragma unroll
            for (int off = 8; off > 0; off >>= 1)
                rs += __shfl_xor_sync(0xffffffffu, rs, off);
            l_i[i] = l_i[i] * alpha + rs;
            m_i[i] = mnew;
#pragma unroll
            for (int j = 0; j < 4; j++) o[i][j] *= alpha;
            Ps[(((tx << 2) + 0) << 6) + (((ty ^ tx) & 15) << 2) + i] = p0;
            Ps[(((tx << 2) + 1) << 6) + (((ty ^ tx) & 15) << 2) + i] = p1;
            Ps[(((tx << 2) + 2) << 6) + (((ty ^ tx) & 15) << 2) + i] = p2;
            Ps[(((tx << 2) + 3) << 6) + (((ty ^ tx) & 15) << 2) + i] = p3;
        }
        __syncthreads();

#pragma unroll 16
        for (int c = 0; c < 64; c++) {
            float4 a  = *(const float4*)&Ps[(c << 6) + (((ty ^ (c >> 2)) & 15) << 2)];
            float4 bb = *(const float4*)&Vs[(c << 6) + (tx << 2)];
            float avv[4] = {a.x, a.y, a.z, a.w};
            float bvv[4] = {bb.x, bb.y, bb.z, bb.w};
#pragma unroll
            for (int i = 0; i < 4; i++)
#pragma unroll
                for (int j = 0; j < 4; j++)
                    o[i][j] += avv[i] * bvv[j];
        }
    }

#pragma unroll
    for (int i = 0; i < 4; i++) {
        float inv = 1.0f / l_i[i];
        float4 ov;
        ov.x = o[i][0] * inv;
        ov.y = o[i][1] * inv;
        ov.z = o[i][2] * inv;
        ov.w = o[i][3] * inv;
        size_t row = (size_t)b * S_ + m0 + (ty << 2) + i;
        *(float4*)&out[row * D_ + h * DH_ + (tx << 2)] = ov;
    }
}

// ---------------------------------------------------------------------------
extern "C" void kernel_launch(void* const* d_in, const int* in_sizes, int n_in,
                              void* d_out, int out_size)
{
    (void)in_sizes; (void)n_in; (void)out_size;
    const float* x    = (const float*)d_in[0];
    const float* Wqkv = (const float*)d_in[2];
    const float* bqkv = (const float*)d_in[3];
    const float* Wp   = (const float*)d_in[4];
    const float* bp   = (const float*)d_in[5];
    float* out = (float*)d_out;

    float* qkv = nullptr; float* att = nullptr;
    __nv_bfloat16 *wqh, *wql, *wph, *wpl;
    cudaGetSymbolAddress((void**)&qkv, g_qkv);
    cudaGetSymbolAddress((void**)&att, g_att);
    cudaGetSymbolAddress((void**)&wqh, g_wqkvT_hi);
    cudaGetSymbolAddress((void**)&wql, g_wqkvT_lo);
    cudaGetSymbolAddress((void**)&wph, g_wpT_hi);
    cudaGetSymbolAddress((void**)&wpl, g_wpT_lo);

    cudaFuncSetAttribute(gemm_mma, cudaFuncAttributeMaxDynamicSharedMemorySize, 65536);
    cudaFuncSetAttribute(flash_attn, cudaFuncAttributeMaxDynamicSharedMemorySize, 65536);

    // Transpose + split weights (bf16 hi/lo)
    wtrans<<<dim3(QKVLD / 32, D_ / 32), dim3(32, 8)>>>(Wqkv, wqh, wql, D_, QKVLD);
    wtrans<<<dim3(D_ / 32, D_ / 32),   dim3(32, 8)>>>(Wp,   wph, wpl, D_, D_);

    const int M = M_TOT;

    // QKV projection (tensor cores, bf16x3)
    gemm_mma<<<dim3(QKVLD / 128, M / 128), 256, 65536>>>(
        x, wqh, wql, bqkv, qkv, M, QKVLD, D_);

    // Causal flash attention -> merged heads
    flash_attn<<<dim3(S_ / 64, H_, B_), 256, 65536>>>(qkv, att);

    // Output projection (tensor cores, bf16x3)
    gemm_mma<<<dim3(D_ / 128, M / 128), 256, 65536>>>(
        att, wph, wpl, bp, out, M, D_, D_);
}

// round 7
// speedup vs baseline: 3.6896x; 1.6826x over previous
#include <cuda_runtime.h>
#include <cuda_bf16.h>
#include <cstdint>

#define B_   2
#define S_   2048
#define D_   768
#define H_   12
#define DH_  64
#define QKVLD (3 * D_)   // 2304
#define M_TOT (B_ * S_)  // 4096

// ---------------------------------------------------------------------------
// Scratch (allocation-free rule: __device__ globals)
// ---------------------------------------------------------------------------
__device__ float g_qkv[(size_t)M_TOT * QKVLD];           // [B*S, 3D]
__device__ float g_att[(size_t)M_TOT * D_];              // [B*S, D]
__device__ __nv_bfloat16 g_wqkvT_hi[(size_t)QKVLD * D_]; // W_qkv^T [2304,768]
__device__ __nv_bfloat16 g_wqkvT_lo[(size_t)QKVLD * D_];
__device__ __nv_bfloat16 g_wpT_hi[(size_t)D_ * D_];      // W_proj^T [768,768]
__device__ __nv_bfloat16 g_wpT_lo[(size_t)D_ * D_];

// ---------------------------------------------------------------------------
// sm_80-level building blocks (compile clean for compute_103)
// ---------------------------------------------------------------------------
__device__ __forceinline__ uint32_t smem_u32(const void* p) {
    uint32_t a;
    asm("{ .reg .u64 t; cvta.to.shared.u64 t, %1; cvt.u32.u64 %0, t; }" : "=r"(a) : "l"(p));
    return a;
}
__device__ __forceinline__ void cp_async16(uint32_t dst, const void* src) {
    asm volatile("cp.async.cg.shared.global [%0], [%1], 16;" :: "r"(dst), "l"(src));
}
__device__ __forceinline__ void cp_commit() { asm volatile("cp.async.commit_group;"); }
__device__ __forceinline__ void cp_wait0()  { asm volatile("cp.async.wait_group 0;"); }

__device__ __forceinline__ void ldm4(uint32_t* r, uint32_t addr) {
    asm volatile("ldmatrix.sync.aligned.m8n8.x4.shared.b16 {%0,%1,%2,%3}, [%4];"
        : "=r"(r[0]), "=r"(r[1]), "=r"(r[2]), "=r"(r[3]) : "r"(addr));
}
__device__ __forceinline__ void ldm2(uint32_t* r, uint32_t addr) {
    asm volatile("ldmatrix.sync.aligned.m8n8.x2.shared.b16 {%0,%1}, [%2];"
        : "=r"(r[0]), "=r"(r[1]) : "r"(addr));
}
__device__ __forceinline__ void ldm2t(uint32_t* r, uint32_t addr) {
    asm volatile("ldmatrix.sync.aligned.m8n8.x2.trans.shared.b16 {%0,%1}, [%2];"
        : "=r"(r[0]), "=r"(r[1]) : "r"(addr));
}
__device__ __forceinline__ void mma16816(float* d, const uint32_t* a, const uint32_t* b) {
    asm volatile(
        "mma.sync.aligned.m16n8k16.row.col.f32.bf16.bf16.f32 "
        "{%0,%1,%2,%3}, {%4,%5,%6,%7}, {%8,%9}, {%0,%1,%2,%3};"
        : "+f"(d[0]), "+f"(d[1]), "+f"(d[2]), "+f"(d[3])
        : "r"(a[0]), "r"(a[1]), "r"(a[2]), "r"(a[3]), "r"(b[0]), "r"(b[1]));
}
__device__ __forceinline__ uint32_t pack_bf2(float a, float b) {
    __nv_bfloat162 t = __floats2bfloat162_rn(a, b);
    return *reinterpret_cast<uint32_t*>(&t);
}

#define SWZOFF(r, g) (((uint32_t)(r) << 7) + (((uint32_t)((g) ^ ((r) & 7))) << 4))

// ---------------------------------------------------------------------------
// Weight transpose + bf16 hi/lo split: W[K,N] -> T{hi,lo}[N,K]
// ---------------------------------------------------------------------------
__global__ void wtrans(const float* __restrict__ W,
                       __nv_bfloat16* __restrict__ Thi,
                       __nv_bfloat16* __restrict__ Tlo, int K, int N)
{
    __shared__ float t[32][33];
    int bx = blockIdx.x << 5;
    int by = blockIdx.y << 5;
    int tx = threadIdx.x, ty = threadIdx.y;
#pragma unroll
    for (int j = 0; j < 4; j++)
        t[ty + j * 8][tx] = W[(size_t)(by + ty + j * 8) * N + bx + tx];
    __syncthreads();
#pragma unroll
    for (int j = 0; j < 4; j++) {
        float v = t[tx][ty + j * 8];
        __nv_bfloat16 hi = __float2bfloat16(v);
        float lo = v - __bfloat162float(hi);
        size_t o = (size_t)(bx + ty + j * 8) * K + by + tx;
        Thi[o] = hi;
        Tlo[o] = __float2bfloat16(lo);
    }
}

// ---------------------------------------------------------------------------
// bf16x3 tensor-core GEMM (unchanged from R5, passing)
// ---------------------------------------------------------------------------
__global__ __launch_bounds__(256) void gemm_mma(
    const float* __restrict__ A,
    const __nv_bfloat16* __restrict__ Bthi,
    const __nv_bfloat16* __restrict__ Btlo,
    const float* __restrict__ bias, float* __restrict__ C,
    int M, int Ntot, int K)
{
    extern __shared__ __align__(1024) uint8_t smem[];
    const uint32_t sb  = smem_u32(smem);
    const uint32_t Ahi = sb, Alo = sb + 16384, Bhi = sb + 32768, Blo = sb + 49152;

    const int tid  = threadIdx.x;
    const int lane = tid & 31;
    const int wid  = tid >> 5;
    const int wm   = wid & 1;
    const int wn   = wid >> 1;
    const int m0   = blockIdx.y << 7;
    const int n0   = blockIdx.x << 7;

    float acc[4][4][4];
#pragma unroll
    for (int mt = 0; mt < 4; mt++)
#pragma unroll
        for (int nt = 0; nt < 4; nt++)
#pragma unroll
            for (int e = 0; e < 4; e++) acc[mt][nt][e] = 0.f;

    const int aRow = lane & 15;
    const int aKs  = lane >> 4;
    const int bRow = lane & 7;
    const int bKs  = (lane >> 3) & 1;

    const int nchunks = K >> 6;
    for (int c = 0; c < nchunks; c++) {
        const int k0 = c << 6;
        __syncthreads();

#pragma unroll
        for (int u = 0; u < 4; u++) {
            int unit = tid + (u << 8);
            int r = unit >> 3, g = unit & 7;
            uint32_t off = SWZOFF(r, g);
            const __nv_bfloat16* sh = Bthi + (size_t)(n0 + r) * K + k0 + (g << 3);
            const __nv_bfloat16* sl = Btlo + (size_t)(n0 + r) * K + k0 + (g << 3);
            cp_async16(Bhi + off, sh);
            cp_async16(Blo + off, sl);
        }
        cp_commit();

#pragma unroll
        for (int u = 0; u < 4; u++) {
            int unit = tid + (u << 8);
            int r = unit >> 3, g = unit & 7;
            const float* ap = A + (size_t)(m0 + r) * K + k0 + (g << 3);
            float4 v0 = *(const float4*)ap;
            float4 v1 = *(const float4*)(ap + 4);
            float f[8] = {v0.x, v0.y, v0.z, v0.w, v1.x, v1.y, v1.z, v1.w};
            float l[8];
#pragma unroll
            for (int e = 0; e < 8; e++) {
                __nv_bfloat16 h = __float2bfloat16(f[e]);
                l[e] = f[e] - __bfloat162float(h);
            }
            uint4 hp, lp;
            hp.x = pack_bf2(f[0], f[1]); hp.y = pack_bf2(f[2], f[3]);
            hp.z = pack_bf2(f[4], f[5]); hp.w = pack_bf2(f[6], f[7]);
            lp.x = pack_bf2(l[0], l[1]); lp.y = pack_bf2(l[2], l[3]);
            lp.z = pack_bf2(l[4], l[5]); lp.w = pack_bf2(l[6], l[7]);
            uint32_t off = SWZOFF(r, g);
            *(uint4*)(smem + off)         = hp;
            *(uint4*)(smem + 16384 + off) = lp;
        }
        cp_wait0();
        __syncthreads();

#pragma unroll
        for (int ks = 0; ks < 4; ks++) {
            const int kc = ks << 1;
            uint32_t ah[4][4], al[4][4];
#pragma unroll
            for (int mt = 0; mt < 4; mt++) {
                int row = (wm << 6) + (mt << 4) + aRow;
                uint32_t off = SWZOFF(row, kc + aKs);
                ldm4(ah[mt], Ahi + off);
                ldm4(al[mt], Alo + off);
            }
            uint32_t bh[4][2], bl[4][2];
#pragma unroll
            for (int nt = 0; nt < 4; nt++) {
                int row = (wn << 5) + (nt << 3) + bRow;
                uint32_t off = SWZOFF(row, kc + bKs);
                ldm2(bh[nt], Bhi + off);
                ldm2(bl[nt], Blo + off);
            }
#pragma unroll
            for (int mt = 0; mt < 4; mt++)
#pragma unroll
                for (int nt = 0; nt < 4; nt++) {
                    mma16816(acc[mt][nt], ah[mt], bh[nt]);
                    mma16816(acc[mt][nt], al[mt], bh[nt]);
                    mma16816(acc[mt][nt], ah[mt], bl[nt]);
                }
        }
    }

#pragma unroll
    for (int mt = 0; mt < 4; mt++) {
        int row = m0 + (wm << 6) + (mt << 4) + (lane >> 2);
#pragma unroll
        for (int nt = 0; nt < 4; nt++) {
            int col = n0 + (wn << 5) + (nt << 3) + ((lane & 3) << 1);
            float2 bv = *(const float2*)&bias[col];
            float2 o0, o1;
            o0.x = acc[mt][nt][0] + bv.x;
            o0.y = acc[mt][nt][1] + bv.y;
            o1.x = acc[mt][nt][2] + bv.x;
            o1.y = acc[mt][nt][3] + bv.y;
            *(float2*)&C[(size_t)row * Ntot + col]       = o0;
            *(float2*)&C[(size_t)(row + 8) * Ntot + col] = o1;
        }
    }
}

// ---------------------------------------------------------------------------
// Flash attention on tensor cores (mma.sync bf16x3), causal.
// BM=128 (8 warps x m16), BN=64, DH=64. Q scaled by 0.125 at staging (exact).
// S = QK^T: K smem [n][k] K-major, B-frags via ldm2 (validated in gemm_mma).
// P-V: S accumulator frags ARE the A-operand frags (pack pairs to bf16 hi/lo);
// V B-frags via ldmatrix.x2.trans from row-major V smem (XOR-chunk swizzle).
// ---------------------------------------------------------------------------
__global__ __launch_bounds__(256) void flash_attn_mma(
    const float* __restrict__ qkv, float* __restrict__ out)
{
    extern __shared__ __align__(1024) uint8_t sm[];
    const uint32_t sb  = smem_u32(sm);
    const uint32_t Qhi = sb,          Qlo = sb + 16384;
    const uint32_t Khi = sb + 32768,  Klo = sb + 40960;
    const uint32_t Vhi = sb + 49152,  Vlo = sb + 57344;

    const int tid  = threadIdx.x;
    const int lane = tid & 31;
    const int wid  = tid >> 5;             // 0..7, m16 tile index
    const int mblk = (int)gridDim.x - 1 - (int)blockIdx.x;  // heavy first
    const int h    = blockIdx.y;
    const int b    = blockIdx.z;
    const int m0   = mblk << 7;

    const float* Qg = qkv + (size_t)b * S_ * QKVLD + h * DH_;
    const float* Kg = Qg + D_;
    const float* Vg = Qg + 2 * D_;

    // ---- stage Q (x 0.125) -> bf16 hi/lo, swizzled ----
#pragma unroll
    for (int u = 0; u < 4; u++) {
        int unit = tid + (u << 8);
        int r = unit >> 3, g = unit & 7;
        const float* ap = Qg + (size_t)(m0 + r) * QKVLD + (g << 3);
        float4 v0 = *(const float4*)ap;
        float4 v1 = *(const float4*)(ap + 4);
        float f[8] = {v0.x, v0.y, v0.z, v0.w, v1.x, v1.y, v1.z, v1.w};
        float l[8];
#pragma unroll
        for (int e = 0; e < 8; e++) {
            f[e] *= 0.125f;
            __nv_bfloat16 hh = __float2bfloat16(f[e]);
            l[e] = f[e] - __bfloat162float(hh);
        }
        uint4 hp, lp;
        hp.x = pack_bf2(f[0], f[1]); hp.y = pack_bf2(f[2], f[3]);
        hp.z = pack_bf2(f[4], f[5]); hp.w = pack_bf2(f[6], f[7]);
        lp.x = pack_bf2(l[0], l[1]); lp.y = pack_bf2(l[2], l[3]);
        lp.z = pack_bf2(l[4], l[5]); lp.w = pack_bf2(l[6], l[7]);
        uint32_t off = SWZOFF(r, g);
        *(uint4*)(sm + off)         = hp;
        *(uint4*)(sm + 16384 + off) = lp;
    }
    __syncthreads();

    // ---- Q fragments (held in registers for whole CTA) ----
    uint32_t qh[4][4], ql[4][4];
    const int aRow = lane & 15;
    const int aKs  = lane >> 4;
#pragma unroll
    for (int ks = 0; ks < 4; ks++) {
        uint32_t off = SWZOFF((wid << 4) + aRow, (ks << 1) + aKs);
        ldm4(qh[ks], Qhi + off);
        ldm4(ql[ks], Qlo + off);
    }

    float o[8][4];
#pragma unroll
    for (int nt = 0; nt < 8; nt++)
#pragma unroll
        for (int e = 0; e < 4; e++) o[nt][e] = 0.f;
    float mrow0 = -1e30f, mrow1 = -1e30f, lrow0 = 0.f, lrow1 = 0.f;

    const int rbase = m0 + (wid << 4) + (lane >> 2);  // row of c0/c1; +8 for c2/c3
    const int nkv = 2 * mblk + 2;

    for (int nb = 0; nb < nkv; nb++) {
        const int n0 = nb << 6;
        __syncthreads();   // protect K/V smem from previous iteration's reads

        // ---- stage K and V (fp32 -> bf16 hi/lo, swizzled) ----
#pragma unroll
        for (int u = 0; u < 2; u++) {
            int unit = tid + (u << 8);
            int r = unit >> 3, g = unit & 7;
            uint32_t off = SWZOFF(r, g);
            {
                const float* ap = Kg + (size_t)(n0 + r) * QKVLD + (g << 3);
                float4 v0 = *(const float4*)ap;
                float4 v1 = *(const float4*)(ap + 4);
                float f[8] = {v0.x, v0.y, v0.z, v0.w, v1.x, v1.y, v1.z, v1.w};
                float l[8];
#pragma unroll
                for (int e = 0; e < 8; e++) {
                    __nv_bfloat16 hh = __float2bfloat16(f[e]);
                    l[e] = f[e] - __bfloat162float(hh);
                }
                uint4 hp, lp;
                hp.x = pack_bf2(f[0], f[1]); hp.y = pack_bf2(f[2], f[3]);
                hp.z = pack_bf2(f[4], f[5]); hp.w = pack_bf2(f[6], f[7]);
                lp.x = pack_bf2(l[0], l[1]); lp.y = pack_bf2(l[2], l[3]);
                lp.z = pack_bf2(l[4], l[5]); lp.w = pack_bf2(l[6], l[7]);
                *(uint4*)(sm + 32768 + off) = hp;
                *(uint4*)(sm + 40960 + off) = lp;
            }
            {
                const float* ap = Vg + (size_t)(n0 + r) * QKVLD + (g << 3);
                float4 v0 = *(const float4*)ap;
                float4 v1 = *(const float4*)(ap + 4);
                float f[8] = {v0.x, v0.y, v0.z, v0.w, v1.x, v1.y, v1.z, v1.w};
                float l[8];
#pragma unroll
                for (int e = 0; e < 8; e++) {
                    __nv_bfloat16 hh = __float2bfloat16(f[e]);
                    l[e] = f[e] - __bfloat162float(hh);
                }
                uint4 hp, lp;
                hp.x = pack_bf2(f[0], f[1]); hp.y = pack_bf2(f[2], f[3]);
                hp.z = pack_bf2(f[4], f[5]); hp.w = pack_bf2(f[6], f[7]);
                lp.x = pack_bf2(l[0], l[1]); lp.y = pack_bf2(l[2], l[3]);
                lp.z = pack_bf2(l[4], l[5]); lp.w = pack_bf2(l[6], l[7]);
                *(uint4*)(sm + 49152 + off) = hp;
                *(uint4*)(sm + 57344 + off) = lp;
            }
        }
        __syncthreads();

        // ---- S = QK^T (bf16x3), 8 n8-tiles x 4 k16 steps ----
        float s[8][4];
#pragma unroll
        for (int nt = 0; nt < 8; nt++)
#pragma unroll
            for (int e = 0; e < 4; e++) s[nt][e] = 0.f;

#pragma unroll
        for (int ks = 0; ks < 4; ks++) {
            const uint32_t kc = (ks << 1) + ((lane >> 3) & 1);
#pragma unroll
            for (int nt = 0; nt < 8; nt++) {
                uint32_t off = SWZOFF((nt << 3) + (lane & 7), kc);
                uint32_t bh[2], bl[2];
                ldm2(bh, Khi + off);
                ldm2(bl, Klo + off);
                mma16816(s[nt], qh[ks], bh);
                mma16816(s[nt], ql[ks], bh);
                mma16816(s[nt], qh[ks], bl);
            }
        }

        // ---- causal mask (fragment level, per-warp uniform) ----
        if (n0 + 63 > m0 + (wid << 4)) {
#pragma unroll
            for (int nt = 0; nt < 8; nt++) {
                int col = n0 + (nt << 3) + ((lane & 3) << 1);
                if (col     > rbase)     s[nt][0] = -1e30f;
                if (col + 1 > rbase)     s[nt][1] = -1e30f;
                if (col     > rbase + 8) s[nt][2] = -1e30f;
                if (col + 1 > rbase + 8) s[nt][3] = -1e30f;
            }
        }

        // ---- online softmax (rows rbase, rbase+8) ----
        float mx0 = s[0][0], mx1 = s[0][2];
#pragma unroll
        for (int nt = 0; nt < 8; nt++) {
            mx0 = fmaxf(mx0, fmaxf(s[nt][0], s[nt][1]));
            mx1 = fmaxf(mx1, fmaxf(s[nt][2], s[nt][3]));
        }
        mx0 = fmaxf(mx0, __shfl_xor_sync(0xffffffffu, mx0, 1));
        mx0 = fmaxf(mx0, __shfl_xor_sync(0xffffffffu, mx0, 2));
        mx1 = fmaxf(mx1, __shfl_xor_sync(0xffffffffu, mx1, 1));
        mx1 = fmaxf(mx1, __shfl_xor_sync(0xffffffffu, mx1, 2));

        float mn0 = fmaxf(mrow0, mx0);
        float mn1 = fmaxf(mrow1, mx1);
        float al0 = __expf(mrow0 - mn0);
        float al1 = __expf(mrow1 - mn1);
        mrow0 = mn0; mrow1 = mn1;

        float rs0 = 0.f, rs1 = 0.f;
#pragma unroll
        for (int nt = 0; nt < 8; nt++) {
            s[nt][0] = __expf(s[nt][0] - mn0);
            s[nt][1] = __expf(s[nt][1] - mn0);
            s[nt][2] = __expf(s[nt][2] - mn1);
            s[nt][3] = __expf(s[nt][3] - mn1);
            rs0 += s[nt][0] + s[nt][1];
            rs1 += s[nt][2] + s[nt][3];
        }
        rs0 += __shfl_xor_sync(0xffffffffu, rs0, 1);
        rs0 += __shfl_xor_sync(0xffffffffu, rs0, 2);
        rs1 += __shfl_xor_sync(0xffffffffu, rs1, 1);
        rs1 += __shfl_xor_sync(0xffffffffu, rs1, 2);
        lrow0 = lrow0 * al0 + rs0;
        lrow1 = lrow1 * al1 + rs1;

#pragma unroll
        for (int nt = 0; nt < 8; nt++) {
            o[nt][0] *= al0; o[nt][1] *= al0;
            o[nt][2] *= al1; o[nt][3] *= al1;
        }

        // ---- O += P @ V (bf16x3); S-frags -> A-frags, V via ldm2.trans ----
#pragma unroll
        for (int ks = 0; ks < 4; ks++) {
            uint32_t pa[4], pl[4];
            {
                float p00 = s[2*ks][0],   p01 = s[2*ks][1];
                float p10 = s[2*ks][2],   p11 = s[2*ks][3];
                float p20 = s[2*ks+1][0], p21 = s[2*ks+1][1];
                float p30 = s[2*ks+1][2], p31 = s[2*ks+1][3];
                __nv_bfloat16 h;
                float q00, q01, q10, q11, q20, q21, q30, q31;
                h = __float2bfloat16(p00); q00 = p00 - __bfloat162float(h);
                h = __float2bfloat16(p01); q01 = p01 - __bfloat162float(h);
                h = __float2bfloat16(p10); q10 = p10 - __bfloat162float(h);
                h = __float2bfloat16(p11); q11 = p11 - __bfloat162float(h);
                h = __float2bfloat16(p20); q20 = p20 - __bfloat162float(h);
                h = __float2bfloat16(p21); q21 = p21 - __bfloat162float(h);
                h = __float2bfloat16(p30); q30 = p30 - __bfloat162float(h);
                h = __float2bfloat16(p31); q31 = p31 - __bfloat162float(h);
                pa[0] = pack_bf2(p00, p01); pa[1] = pack_bf2(p10, p11);
                pa[2] = pack_bf2(p20, p21); pa[3] = pack_bf2(p30, p31);
                pl[0] = pack_bf2(q00, q01); pl[1] = pack_bf2(q10, q11);
                pl[2] = pack_bf2(q20, q21); pl[3] = pack_bf2(q30, q31);
            }
            const uint32_t vrow = (ks << 4) + (lane & 15);
#pragma unroll
            for (int nt = 0; nt < 8; nt++) {
                uint32_t off = SWZOFF(vrow, nt);
                uint32_t vh[2], vl[2];
                ldm2t(vh, Vhi + off);
                ldm2t(vl, Vlo + off);
                mma16816(o[nt], pa, vh);
                mma16816(o[nt], pl, vh);
                mma16816(o[nt], pa, vl);
            }
        }
    }

    // ---- epilogue: normalize, write merged-head layout ----
    float inv0 = 1.0f / lrow0;
    float inv1 = 1.0f / lrow1;
    int r0 = (size_t)0 + m0 + (wid << 4) + (lane >> 2);
#pragma unroll
    for (int nt = 0; nt < 8; nt++) {
        int col = h * DH_ + (nt << 3) + ((lane & 3) << 1);
        float2 o0, o1;
        o0.x = o[nt][0] * inv0; o0.y = o[nt][1] * inv0;
        o1.x = o[nt][2] * inv1; o1.y = o[nt][3] * inv1;
        *(float2*)&out[((size_t)b * S_ + r0) * D_ + col]     = o0;
        *(float2*)&out[((size_t)b * S_ + r0 + 8) * D_ + col] = o1;
    }
}

// ---------------------------------------------------------------------------
extern "C" void kernel_launch(void* const* d_in, const int* in_sizes, int n_in,
                              void* d_out, int out_size)
{
    (void)in_sizes; (void)n_in; (void)out_size;
    const float* x    = (const float*)d_in[0];
    const float* Wqkv = (const float*)d_in[2];
    const float* bqkv = (const float*)d_in[3];
    const float* Wp   = (const float*)d_in[4];
    const float* bp   = (const float*)d_in[5];
    float* out = (float*)d_out;

    float* qkv = nullptr; float* att = nullptr;
    __nv_bfloat16 *wqh, *wql, *wph, *wpl;
    cudaGetSymbolAddress((void**)&qkv, g_qkv);
    cudaGetSymbolAddress((void**)&att, g_att);
    cudaGetSymbolAddress((void**)&wqh, g_wqkvT_hi);
    cudaGetSymbolAddress((void**)&wql, g_wqkvT_lo);
    cudaGetSymbolAddress((void**)&wph, g_wpT_hi);
    cudaGetSymbolAddress((void**)&wpl, g_wpT_lo);

    cudaFuncSetAttribute(gemm_mma, cudaFuncAttributeMaxDynamicSharedMemorySize, 65536);
    cudaFuncSetAttribute(flash_attn_mma, cudaFuncAttributeMaxDynamicSharedMemorySize, 65536);

    // Transpose + split weights (bf16 hi/lo)
    wtrans<<<dim3(QKVLD / 32, D_ / 32), dim3(32, 8)>>>(Wqkv, wqh, wql, D_, QKVLD);
    wtrans<<<dim3(D_ / 32, D_ / 32),   dim3(32, 8)>>>(Wp,   wph, wpl, D_, D_);

    const int M = M_TOT;

    // QKV projection (tensor cores, bf16x3)
    gemm_mma<<<dim3(QKVLD / 128, M / 128), 256, 65536>>>(
        x, wqh, wql, bqkv, qkv, M, QKVLD, D_);

    // Causal flash attention on tensor cores -> merged heads
    flash_attn_mma<<<dim3(S_ / 128, H_, B_), 256, 65536>>>(qkv, att);

    // Output projection (tensor cores, bf16x3)
    gemm_mma<<<dim3(D_ / 128, M / 128), 256, 65536>>>(
        att, wph, wpl, bp, out, M, D_, D_);
}

// round 11
// speedup vs baseline: 4.6436x; 1.2586x over previous
#include <cuda_runtime.h>
#include <cuda_bf16.h>
#include <cstdint>

#define B_   2
#define S_   2048
#define D_   768
#define H_   12
#define DH_  64
#define QKVLD (3 * D_)   // 2304
#define M_TOT (B_ * S_)  // 4096

// ---------------------------------------------------------------------------
// Scratch (allocation-free rule: __device__ globals)
// ---------------------------------------------------------------------------
__device__ float g_qkv[(size_t)M_TOT * QKVLD];           // [B*S, 3D]
__device__ float g_att[(size_t)M_TOT * D_];              // [B*S, D]
__device__ __nv_bfloat16 g_wqkvT_hi[(size_t)QKVLD * D_]; // W_qkv^T [2304,768]
__device__ __nv_bfloat16 g_wqkvT_lo[(size_t)QKVLD * D_];
__device__ __nv_bfloat16 g_wpT_hi[(size_t)D_ * D_];      // W_proj^T [768,768]
__device__ __nv_bfloat16 g_wpT_lo[(size_t)D_ * D_];

// ---------------------------------------------------------------------------
// sm_80-level building blocks (compile clean for compute_103)
// ---------------------------------------------------------------------------
__device__ __forceinline__ uint32_t smem_u32(const void* p) {
    uint32_t a;
    asm("{ .reg .u64 t; cvta.to.shared.u64 t, %1; cvt.u32.u64 %0, t; }" : "=r"(a) : "l"(p));
    return a;
}
__device__ __forceinline__ void cp_async16(uint32_t dst, const void* src) {
    asm volatile("cp.async.cg.shared.global [%0], [%1], 16;" :: "r"(dst), "l"(src));
}
__device__ __forceinline__ void cp_commit() { asm volatile("cp.async.commit_group;"); }
__device__ __forceinline__ void cp_wait0()  { asm volatile("cp.async.wait_group 0;"); }

__device__ __forceinline__ void ldm4(uint32_t* r, uint32_t addr) {
    asm volatile("ldmatrix.sync.aligned.m8n8.x4.shared.b16 {%0,%1,%2,%3}, [%4];"
        : "=r"(r[0]), "=r"(r[1]), "=r"(r[2]), "=r"(r[3]) : "r"(addr));
}
__device__ __forceinline__ void ldm2(uint32_t* r, uint32_t addr) {
    asm volatile("ldmatrix.sync.aligned.m8n8.x2.shared.b16 {%0,%1}, [%2];"
        : "=r"(r[0]), "=r"(r[1]) : "r"(addr));
}
__device__ __forceinline__ void ldm2t(uint32_t* r, uint32_t addr) {
    asm volatile("ldmatrix.sync.aligned.m8n8.x2.trans.shared.b16 {%0,%1}, [%2];"
        : "=r"(r[0]), "=r"(r[1]) : "r"(addr));
}
__device__ __forceinline__ void mma16816(float* d, const uint32_t* a, const uint32_t* b) {
    asm volatile(
        "mma.sync.aligned.m16n8k16.row.col.f32.bf16.bf16.f32 "
        "{%0,%1,%2,%3}, {%4,%5,%6,%7}, {%8,%9}, {%0,%1,%2,%3};"
        : "+f"(d[0]), "+f"(d[1]), "+f"(d[2]), "+f"(d[3])
        : "r"(a[0]), "r"(a[1]), "r"(a[2]), "r"(a[3]), "r"(b[0]), "r"(b[1]));
}
__device__ __forceinline__ uint32_t pack_bf2(float a, float b) {
    __nv_bfloat162 t = __floats2bfloat162_rn(a, b);
    return *reinterpret_cast<uint32_t*>(&t);
}

#define SWZOFF(r, g) (((uint32_t)(r) << 7) + (((uint32_t)((g) ^ ((r) & 7))) << 4))

// ---------------------------------------------------------------------------
// Weight transpose + bf16 hi/lo split: W[K,N] -> T{hi,lo}[N,K]
// ---------------------------------------------------------------------------
__global__ void wtrans(const float* __restrict__ W,
                       __nv_bfloat16* __restrict__ Thi,
                       __nv_bfloat16* __restrict__ Tlo, int K, int N)
{
    __shared__ float t[32][33];
    int bx = blockIdx.x << 5;
    int by = blockIdx.y << 5;
    int tx = threadIdx.x, ty = threadIdx.y;
#pragma unroll
    for (int j = 0; j < 4; j++)
        t[ty + j * 8][tx] = W[(size_t)(by + ty + j * 8) * N + bx + tx];
    __syncthreads();
#pragma unroll
    for (int j = 0; j < 4; j++) {
        float v = t[tx][ty + j * 8];
        __nv_bfloat16 hi = __float2bfloat16(v);
        float lo = v - __bfloat162float(hi);
        size_t o = (size_t)(bx + ty + j * 8) * K + by + tx;
        Thi[o] = hi;
        Tlo[o] = __float2bfloat16(lo);
    }
}

// ---------------------------------------------------------------------------
// bf16x3 tensor-core GEMM: now __launch_bounds__(256,2) for 2 CTAs/SM
// ---------------------------------------------------------------------------
__global__ __launch_bounds__(256, 2) void gemm_mma(
    const float* __restrict__ A,
    const __nv_bfloat16* __restrict__ Bthi,
    const __nv_bfloat16* __restrict__ Btlo,
    const float* __restrict__ bias, float* __restrict__ C,
    int M, int Ntot, int K)
{
    extern __shared__ __align__(1024) uint8_t smem[];
    const uint32_t sb  = smem_u32(smem);
    const uint32_t Ahi = sb, Alo = sb + 16384, Bhi = sb + 32768, Blo = sb + 49152;

    const int tid  = threadIdx.x;
    const int lane = tid & 31;
    const int wid  = tid >> 5;
    const int wm   = wid & 1;
    const int wn   = wid >> 1;
    const int m0   = blockIdx.y << 7;
    const int n0   = blockIdx.x << 7;

    float acc[4][4][4];
#pragma unroll
    for (int mt = 0; mt < 4; mt++)
#pragma unroll
        for (int nt = 0; nt < 4; nt++)
#pragma unroll
            for (int e = 0; e < 4; e++) acc[mt][nt][e] = 0.f;

    const int aRow = lane & 15;
    const int aKs  = lane >> 4;
    const int bRow = lane & 7;
    const int bKs  = (lane >> 3) & 1;

    const int nchunks = K >> 6;
    for (int c = 0; c < nchunks; c++) {
        const int k0 = c << 6;
        __syncthreads();

#pragma unroll
        for (int u = 0; u < 4; u++) {
            int unit = tid + (u << 8);
            int r = unit >> 3, g = unit & 7;
            uint32_t off = SWZOFF(r, g);
            const __nv_bfloat16* sh = Bthi + (size_t)(n0 + r) * K + k0 + (g << 3);
            const __nv_bfloat16* sl = Btlo + (size_t)(n0 + r) * K + k0 + (g << 3);
            cp_async16(Bhi + off, sh);
            cp_async16(Blo + off, sl);
        }
        cp_commit();

#pragma unroll
        for (int u = 0; u < 4; u++) {
            int unit = tid + (u << 8);
            int r = unit >> 3, g = unit & 7;
            const float* ap = A + (size_t)(m0 + r) * K + k0 + (g << 3);
            float4 v0 = *(const float4*)ap;
            float4 v1 = *(const float4*)(ap + 4);
            float f[8] = {v0.x, v0.y, v0.z, v0.w, v1.x, v1.y, v1.z, v1.w};
            float l[8];
#pragma unroll
            for (int e = 0; e < 8; e++) {
                __nv_bfloat16 h = __float2bfloat16(f[e]);
                l[e] = f[e] - __bfloat162float(h);
            }
            uint4 hp, lp;
            hp.x = pack_bf2(f[0], f[1]); hp.y = pack_bf2(f[2], f[3]);
            hp.z = pack_bf2(f[4], f[5]); hp.w = pack_bf2(f[6], f[7]);
            lp.x = pack_bf2(l[0], l[1]); lp.y = pack_bf2(l[2], l[3]);
            lp.z = pack_bf2(l[4], l[5]); lp.w = pack_bf2(l[6], l[7]);
            uint32_t off = SWZOFF(r, g);
            *(uint4*)(smem + off)         = hp;
            *(uint4*)(smem + 16384 + off) = lp;
        }
        cp_wait0();
        __syncthreads();

#pragma unroll
        for (int ks = 0; ks < 4; ks++) {
            const int kc = ks << 1;
            uint32_t ah[4][4], al[4][4];
#pragma unroll
            for (int mt = 0; mt < 4; mt++) {
                int row = (wm << 6) + (mt << 4) + aRow;
                uint32_t off = SWZOFF(row, kc + aKs);
                ldm4(ah[mt], Ahi + off);
                ldm4(al[mt], Alo + off);
            }
            uint32_t bh[4][2], bl[4][2];
#pragma unroll
            for (int nt = 0; nt < 4; nt++) {
                int row = (wn << 5) + (nt << 3) + bRow;
                uint32_t off = SWZOFF(row, kc + bKs);
                ldm2(bh[nt], Bhi + off);
                ldm2(bl[nt], Blo + off);
            }
#pragma unroll
            for (int mt = 0; mt < 4; mt++)
#pragma unroll
                for (int nt = 0; nt < 4; nt++) {
                    mma16816(acc[mt][nt], ah[mt], bh[nt]);
                    mma16816(acc[mt][nt], al[mt], bh[nt]);
                    mma16816(acc[mt][nt], ah[mt], bl[nt]);
                }
        }
    }

#pragma unroll
    for (int mt = 0; mt < 4; mt++) {
        int row = m0 + (wm << 6) + (mt << 4) + (lane >> 2);
#pragma unroll
        for (int nt = 0; nt < 4; nt++) {
            int col = n0 + (wn << 5) + (nt << 3) + ((lane & 3) << 1);
            float2 bv = *(const float2*)&bias[col];
            float2 o0, o1;
            o0.x = acc[mt][nt][0] + bv.x;
            o0.y = acc[mt][nt][1] + bv.y;
            o1.x = acc[mt][nt][2] + bv.x;
            o1.y = acc[mt][nt][3] + bv.y;
            *(float2*)&C[(size_t)row * Ntot + col]       = o0;
            *(float2*)&C[(size_t)(row + 8) * Ntot + col] = o1;
        }
    }
}

// ---------------------------------------------------------------------------
// Flash attention on tensor cores (mma.sync bf16x3), causal.
// SMEM UNION (32KB total): prologue uses [0,32K) for Q hi/lo; after Q frags
// are register-resident, mainloop reuses the same 32KB for K/V hi/lo.
// -> 2 CTAs/SM with __launch_bounds__(256,2).
// ---------------------------------------------------------------------------
__global__ __launch_bounds__(256, 2) void flash_attn_mma(
    const float* __restrict__ qkv, float* __restrict__ out)
{
    extern __shared__ __align__(1024) uint8_t sm[];
    const uint32_t sb  = smem_u32(sm);
    // prologue: Qhi = sb+0 (16KB), Qlo = sb+16384 (16KB)
    // mainloop: Khi = sb+0 (8KB), Klo = sb+8192, Vhi = sb+16384, Vlo = sb+24576
    const uint32_t Qhi = sb,          Qlo = sb + 16384;
    const uint32_t Khi = sb,          Klo = sb + 8192;
    const uint32_t Vhi = sb + 16384,  Vlo = sb + 24576;

    const int tid  = threadIdx.x;
    const int lane = tid & 31;
    const int wid  = tid >> 5;             // 0..7, m16 tile index
    const int mblk = (int)gridDim.x - 1 - (int)blockIdx.x;  // heavy first
    const int h    = blockIdx.y;
    const int b    = blockIdx.z;
    const int m0   = mblk << 7;

    const float* Qg = qkv + (size_t)b * S_ * QKVLD + h * DH_;
    const float* Kg = Qg + D_;
    const float* Vg = Qg + 2 * D_;

    // ---- stage Q (x 0.125) -> bf16 hi/lo, swizzled ----
#pragma unroll
    for (int u = 0; u < 4; u++) {
        int unit = tid + (u << 8);
        int r = unit >> 3, g = unit & 7;
        const float* ap = Qg + (size_t)(m0 + r) * QKVLD + (g << 3);
        float4 v0 = *(const float4*)ap;
        float4 v1 = *(const float4*)(ap + 4);
        float f[8] = {v0.x, v0.y, v0.z, v0.w, v1.x, v1.y, v1.z, v1.w};
        float l[8];
#pragma unroll
        for (int e = 0; e < 8; e++) {
            f[e] *= 0.125f;
            __nv_bfloat16 hh = __float2bfloat16(f[e]);
            l[e] = f[e] - __bfloat162float(hh);
        }
        uint4 hp, lp;
        hp.x = pack_bf2(f[0], f[1]); hp.y = pack_bf2(f[2], f[3]);
        hp.z = pack_bf2(f[4], f[5]); hp.w = pack_bf2(f[6], f[7]);
        lp.x = pack_bf2(l[0], l[1]); lp.y = pack_bf2(l[2], l[3]);
        lp.z = pack_bf2(l[4], l[5]); lp.w = pack_bf2(l[6], l[7]);
        uint32_t off = SWZOFF(r, g);
        *(uint4*)(sm + off)         = hp;
        *(uint4*)(sm + 16384 + off) = lp;
    }
    __syncthreads();

    // ---- Q fragments (held in registers for whole CTA) ----
    uint32_t qh[4][4], ql[4][4];
    const int aRow = lane & 15;
    const int aKs  = lane >> 4;
#pragma unroll
    for (int ks = 0; ks < 4; ks++) {
        uint32_t off = SWZOFF((wid << 4) + aRow, (ks << 1) + aKs);
        ldm4(qh[ks], Qhi + off);
        ldm4(ql[ks], Qlo + off);
    }

    float o[8][4];
#pragma unroll
    for (int nt = 0; nt < 8; nt++)
#pragma unroll
        for (int e = 0; e < 4; e++) o[nt][e] = 0.f;
    float mrow0 = -1e30f, mrow1 = -1e30f, lrow0 = 0.f, lrow1 = 0.f;

    const int rbase = m0 + (wid << 4) + (lane >> 2);  // row of c0/c1; +8 for c2/c3
    const int nkv = 2 * mblk + 2;

    for (int nb = 0; nb < nkv; nb++) {
        const int n0 = nb << 6;
        __syncthreads();   // protect K/V smem (and Q region on first iter)

        // ---- stage K and V (fp32 -> bf16 hi/lo, swizzled) ----
#pragma unroll
        for (int u = 0; u < 2; u++) {
            int unit = tid + (u << 8);
            int r = unit >> 3, g = unit & 7;
            uint32_t off = SWZOFF(r, g);
            {
                const float* ap = Kg + (size_t)(n0 + r) * QKVLD + (g << 3);
                float4 v0 = *(const float4*)ap;
                float4 v1 = *(const float4*)(ap + 4);
                float f[8] = {v0.x, v0.y, v0.z, v0.w, v1.x, v1.y, v1.z, v1.w};
                float l[8];
#pragma unroll
                for (int e = 0; e < 8; e++) {
                    __nv_bfloat16 hh = __float2bfloat16(f[e]);
                    l[e] = f[e] - __bfloat162float(hh);
                }
                uint4 hp, lp;
                hp.x = pack_bf2(f[0], f[1]); hp.y = pack_bf2(f[2], f[3]);
                hp.z = pack_bf2(f[4], f[5]); hp.w = pack_bf2(f[6], f[7]);
                lp.x = pack_bf2(l[0], l[1]); lp.y = pack_bf2(l[2], l[3]);
                lp.z = pack_bf2(l[4], l[5]); lp.w = pack_bf2(l[6], l[7]);
                *(uint4*)(sm + 0    + off) = hp;   // Khi
                *(uint4*)(sm + 8192 + off) = lp;   // Klo
            }
            {
                const float* ap = Vg + (size_t)(n0 + r) * QKVLD + (g << 3);
                float4 v0 = *(const float4*)ap;
                float4 v1 = *(const float4*)(ap + 4);
                float f[8] = {v0.x, v0.y, v0.z, v0.w, v1.x, v1.y, v1.z, v1.w};
                float l[8];
#pragma unroll
                for (int e = 0; e < 8; e++) {
                    __nv_bfloat16 hh = __float2bfloat16(f[e]);
                    l[e] = f[e] - __bfloat162float(hh);
                }
                uint4 hp, lp;
                hp.x = pack_bf2(f[0], f[1]); hp.y = pack_bf2(f[2], f[3]);
                hp.z = pack_bf2(f[4], f[5]); hp.w = pack_bf2(f[6], f[7]);
                lp.x = pack_bf2(l[0], l[1]); lp.y = pack_bf2(l[2], l[3]);
                lp.z = pack_bf2(l[4], l[5]); lp.w = pack_bf2(l[6], l[7]);
                *(uint4*)(sm + 16384 + off) = hp;  // Vhi
                *(uint4*)(sm + 24576 + off) = lp;  // Vlo
            }
        }
        __syncthreads();

        // ---- S = QK^T (bf16x3), 8 n8-tiles x 4 k16 steps ----
        float s[8][4];
#pragma unroll
        for (int nt = 0; nt < 8; nt++)
#pragma unroll
            for (int e = 0; e < 4; e++) s[nt][e] = 0.f;

#pragma unroll
        for (int ks = 0; ks < 4; ks++) {
            const uint32_t kc = (ks << 1) + ((lane >> 3) & 1);
#pragma unroll
            for (int nt = 0; nt < 8; nt++) {
                uint32_t off = SWZOFF((nt << 3) + (lane & 7), kc);
                uint32_t bh[2], bl[2];
                ldm2(bh, Khi + off);
                ldm2(bl, Klo + off);
                mma16816(s[nt], qh[ks], bh);
                mma16816(s[nt], ql[ks], bh);
                mma16816(s[nt], qh[ks], bl);
            }
        }

        // ---- causal mask (fragment level, per-warp uniform) ----
        if (n0 + 63 > m0 + (wid << 4)) {
#pragma unroll
            for (int nt = 0; nt < 8; nt++) {
                int col = n0 + (nt << 3) + ((lane & 3) << 1);
                if (col     > rbase)     s[nt][0] = -1e30f;
                if (col + 1 > rbase)     s[nt][1] = -1e30f;
                if (col     > rbase + 8) s[nt][2] = -1e30f;
                if (col + 1 > rbase + 8) s[nt][3] = -1e30f;
            }
        }

        // ---- online softmax (rows rbase, rbase+8) ----
        float mx0 = s[0][0], mx1 = s[0][2];
#pragma unroll
        for (int nt = 0; nt < 8; nt++) {
            mx0 = fmaxf(mx0, fmaxf(s[nt][0], s[nt][1]));
            mx1 = fmaxf(mx1, fmaxf(s[nt][2], s[nt][3]));
        }
        mx0 = fmaxf(mx0, __shfl_xor_sync(0xffffffffu, mx0, 1));
        mx0 = fmaxf(mx0, __shfl_xor_sync(0xffffffffu, mx0, 2));
        mx1 = fmaxf(mx1, __shfl_xor_sync(0xffffffffu, mx1, 1));
        mx1 = fmaxf(mx1, __shfl_xor_sync(0xffffffffu, mx1, 2));

        float mn0 = fmaxf(mrow0, mx0);
        float mn1 = fmaxf(mrow1, mx1);
        float al0 = __expf(mrow0 - mn0);
        float al1 = __expf(mrow1 - mn1);
        mrow0 = mn0; mrow1 = mn1;

        float rs0 = 0.f, rs1 = 0.f;
#pragma unroll
        for (int nt = 0; nt < 8; nt++) {
            s[nt][0] = __expf(s[nt][0] - mn0);
            s[nt][1] = __expf(s[nt][1] - mn0);
            s[nt][2] = __expf(s[nt][2] - mn1);
            s[nt][3] = __expf(s[nt][3] - mn1);
            rs0 += s[nt][0] + s[nt][1];
            rs1 += s[nt][2] + s[nt][3];
        }
        rs0 += __shfl_xor_sync(0xffffffffu, rs0, 1);
        rs0 += __shfl_xor_sync(0xffffffffu, rs0, 2);
        rs1 += __shfl_xor_sync(0xffffffffu, rs1, 1);
        rs1 += __shfl_xor_sync(0xffffffffu, rs1, 2);
        lrow0 = lrow0 * al0 + rs0;
        lrow1 = lrow1 * al1 + rs1;

#pragma unroll
        for (int nt = 0; nt < 8; nt++) {
            o[nt][0] *= al0; o[nt][1] *= al0;
            o[nt][2] *= al1; o[nt][3] *= al1;
        }

        // ---- O += P @ V (bf16x3); S-frags -> A-frags, V via ldm2.trans ----
#pragma unroll
        for (int ks = 0; ks < 4; ks++) {
            uint32_t pa[4], pl[4];
            {
                float p00 = s[2*ks][0],   p01 = s[2*ks][1];
                float p10 = s[2*ks][2],   p11 = s[2*ks][3];
                float p20 = s[2*ks+1][0], p21 = s[2*ks+1][1];
                float p30 = s[2*ks+1][2], p31 = s[2*ks+1][3];
                __nv_bfloat16 h;
                float q00, q01, q10, q11, q20, q21, q30, q31;
                h = __float2bfloat16(p00); q00 = p00 - __bfloat162float(h);
                h = __float2bfloat16(p01); q01 = p01 - __bfloat162float(h);
                h = __float2bfloat16(p10); q10 = p10 - __bfloat162float(h);
                h = __float2bfloat16(p11); q11 = p11 - __bfloat162float(h);
                h = __float2bfloat16(p20); q20 = p20 - __bfloat162float(h);
                h = __float2bfloat16(p21); q21 = p21 - __bfloat162float(h);
                h = __float2bfloat16(p30); q30 = p30 - __bfloat162float(h);
                h = __float2bfloat16(p31); q31 = p31 - __bfloat162float(h);
                pa[0] = pack_bf2(p00, p01); pa[1] = pack_bf2(p10, p11);
                pa[2] = pack_bf2(p20, p21); pa[3] = pack_bf2(p30, p31);
                pl[0] = pack_bf2(q00, q01); pl[1] = pack_bf2(q10, q11);
                pl[2] = pack_bf2(q20, q21); pl[3] = pack_bf2(q30, q31);
            }
            const uint32_t vrow = (ks << 4) + (lane & 15);
#pragma unroll
            for (int nt = 0; nt < 8; nt++) {
                uint32_t off = SWZOFF(vrow, nt);
                uint32_t vh[2], vl[2];
                ldm2t(vh, Vhi + off);
                ldm2t(vl, Vlo + off);
                mma16816(o[nt], pa, vh);
                mma16816(o[nt], pl, vh);
                mma16816(o[nt], pa, vl);
            }
        }
    }

    // ---- epilogue: normalize, write merged-head layout ----
    float inv0 = 1.0f / lrow0;
    float inv1 = 1.0f / lrow1;
    int r0 = m0 + (wid << 4) + (lane >> 2);
#pragma unroll
    for (int nt = 0; nt < 8; nt++) {
        int col = h * DH_ + (nt << 3) + ((lane & 3) << 1);
        float2 o0, o1;
        o0.x = o[nt][0] * inv0; o0.y = o[nt][1] * inv0;
        o1.x = o[nt][2] * inv1; o1.y = o[nt][3] * inv1;
        *(float2*)&out[((size_t)b * S_ + r0) * D_ + col]     = o0;
        *(float2*)&out[((size_t)b * S_ + r0 + 8) * D_ + col] = o1;
    }
}

// ---------------------------------------------------------------------------
extern "C" void kernel_launch(void* const* d_in, const int* in_sizes, int n_in,
                              void* d_out, int out_size)
{
    (void)in_sizes; (void)n_in; (void)out_size;
    const float* x    = (const float*)d_in[0];
    const float* Wqkv = (const float*)d_in[2];
    const float* bqkv = (const float*)d_in[3];
    const float* Wp   = (const float*)d_in[4];
    const float* bp   = (const float*)d_in[5];
    float* out = (float*)d_out;

    float* qkv = nullptr; float* att = nullptr;
    __nv_bfloat16 *wqh, *wql, *wph, *wpl;
    cudaGetSymbolAddress((void**)&qkv, g_qkv);
    cudaGetSymbolAddress((void**)&att, g_att);
    cudaGetSymbolAddress((void**)&wqh, g_wqkvT_hi);
    cudaGetSymbolAddress((void**)&wql, g_wqkvT_lo);
    cudaGetSymbolAddress((void**)&wph, g_wpT_hi);
    cudaGetSymbolAddress((void**)&wpl, g_wpT_lo);

    cudaFuncSetAttribute(gemm_mma, cudaFuncAttributeMaxDynamicSharedMemorySize, 65536);
    cudaFuncSetAttribute(flash_attn_mma, cudaFuncAttributeMaxDynamicSharedMemorySize, 32768);

    // Transpose + split weights (bf16 hi/lo)
    wtrans<<<dim3(QKVLD / 32, D_ / 32), dim3(32, 8)>>>(Wqkv, wqh, wql, D_, QKVLD);
    wtrans<<<dim3(D_ / 32, D_ / 32),   dim3(32, 8)>>>(Wp,   wph, wpl, D_, D_);

    const int M = M_TOT;

    // QKV projection (tensor cores, bf16x3)
    gemm_mma<<<dim3(QKVLD / 128, M / 128), 256, 65536>>>(
        x, wqh, wql, bqkv, qkv, M, QKVLD, D_);

    // Causal flash attention on tensor cores -> merged heads
    flash_attn_mma<<<dim3(S_ / 128, H_, B_), 256, 32768>>>(qkv, att);

    // Output projection (tensor cores, bf16x3)
    gemm_mma<<<dim3(D_ / 128, M / 128), 256, 65536>>>(
        att, wph, wpl, bp, out, M, D_, D_);
}

// round 12
// speedup vs baseline: 4.6489x; 1.0011x over previous
#include <cuda_runtime.h>
#include <cuda_bf16.h>
#include <cstdint>

#define B_   2
#define S_   2048
#define D_   768
#define H_   12
#define DH_  64
#define QKVLD (3 * D_)   // 2304
#define M_TOT (B_ * S_)  // 4096

// ---------------------------------------------------------------------------
// Scratch (allocation-free rule: __device__ globals)
// All intermediates are bf16 hi/lo pairs (value = hi + lo, err ~2^-16).
// ---------------------------------------------------------------------------
__device__ __nv_bfloat16 g_qkv_hi[(size_t)M_TOT * QKVLD]; // Q pre-scaled x0.125
__device__ __nv_bfloat16 g_qkv_lo[(size_t)M_TOT * QKVLD];
__device__ __nv_bfloat16 g_att_hi[(size_t)M_TOT * D_];
__device__ __nv_bfloat16 g_att_lo[(size_t)M_TOT * D_];
__device__ __nv_bfloat16 g_wqkvT_hi[(size_t)QKVLD * D_];  // W_qkv^T [2304,768]
__device__ __nv_bfloat16 g_wqkvT_lo[(size_t)QKVLD * D_];
__device__ __nv_bfloat16 g_wpT_hi[(size_t)D_ * D_];       // W_proj^T [768,768]
__device__ __nv_bfloat16 g_wpT_lo[(size_t)D_ * D_];

// ---------------------------------------------------------------------------
// sm_80-level building blocks (compile clean for compute_103)
// ---------------------------------------------------------------------------
__device__ __forceinline__ uint32_t smem_u32(const void* p) {
    uint32_t a;
    asm("{ .reg .u64 t; cvta.to.shared.u64 t, %1; cvt.u32.u64 %0, t; }" : "=r"(a) : "l"(p));
    return a;
}
__device__ __forceinline__ void cp_async16(uint32_t dst, const void* src) {
    asm volatile("cp.async.cg.shared.global [%0], [%1], 16;" :: "r"(dst), "l"(src));
}
__device__ __forceinline__ void cp_commit() { asm volatile("cp.async.commit_group;"); }
__device__ __forceinline__ void cp_wait0()  { asm volatile("cp.async.wait_group 0;"); }

__device__ __forceinline__ void ldm4(uint32_t* r, uint32_t addr) {
    asm volatile("ldmatrix.sync.aligned.m8n8.x4.shared.b16 {%0,%1,%2,%3}, [%4];"
        : "=r"(r[0]), "=r"(r[1]), "=r"(r[2]), "=r"(r[3]) : "r"(addr));
}
__device__ __forceinline__ void ldm2(uint32_t* r, uint32_t addr) {
    asm volatile("ldmatrix.sync.aligned.m8n8.x2.shared.b16 {%0,%1}, [%2];"
        : "=r"(r[0]), "=r"(r[1]) : "r"(addr));
}
__device__ __forceinline__ void ldm2t(uint32_t* r, uint32_t addr) {
    asm volatile("ldmatrix.sync.aligned.m8n8.x2.trans.shared.b16 {%0,%1}, [%2];"
        : "=r"(r[0]), "=r"(r[1]) : "r"(addr));
}
__device__ __forceinline__ void mma16816(float* d, const uint32_t* a, const uint32_t* b) {
    asm volatile(
        "mma.sync.aligned.m16n8k16.row.col.f32.bf16.bf16.f32 "
        "{%0,%1,%2,%3}, {%4,%5,%6,%7}, {%8,%9}, {%0,%1,%2,%3};"
        : "+f"(d[0]), "+f"(d[1]), "+f"(d[2]), "+f"(d[3])
        : "r"(a[0]), "r"(a[1]), "r"(a[2]), "r"(a[3]), "r"(b[0]), "r"(b[1]));
}
__device__ __forceinline__ uint32_t pack_bf2(float a, float b) {
    __nv_bfloat162 t = __floats2bfloat162_rn(a, b);
    return *reinterpret_cast<uint32_t*>(&t);
}
__device__ __forceinline__ void split2(float x, float y, uint32_t& hi, uint32_t& lo) {
    __nv_bfloat16 hx = __float2bfloat16(x);
    __nv_bfloat16 hy = __float2bfloat16(y);
    hi = pack_bf2(x, y);
    lo = pack_bf2(x - __bfloat162float(hx), y - __bfloat162float(hy));
}

#define SWZOFF(r, g) (((uint32_t)(r) << 7) + (((uint32_t)((g) ^ ((r) & 7))) << 4))

// ---------------------------------------------------------------------------
// Weight transpose + bf16 hi/lo split: W[K,N] -> T{hi,lo}[N,K]
// ---------------------------------------------------------------------------
__global__ void wtrans(const float* __restrict__ W,
                       __nv_bfloat16* __restrict__ Thi,
                       __nv_bfloat16* __restrict__ Tlo, int K, int N)
{
    __shared__ float t[32][33];
    int bx = blockIdx.x << 5;
    int by = blockIdx.y << 5;
    int tx = threadIdx.x, ty = threadIdx.y;
#pragma unroll
    for (int j = 0; j < 4; j++)
        t[ty + j * 8][tx] = W[(size_t)(by + ty + j * 8) * N + bx + tx];
    __syncthreads();
#pragma unroll
    for (int j = 0; j < 4; j++) {
        float v = t[tx][ty + j * 8];
        __nv_bfloat16 hi = __float2bfloat16(v);
        float lo = v - __bfloat162float(hi);
        size_t o = (size_t)(bx + ty + j * 8) * K + by + tx;
        Thi[o] = hi;
        Tlo[o] = __float2bfloat16(lo);
    }
}

// ---------------------------------------------------------------------------
// GEMM-1 (QKV): A fp32 (x), B pre-split bf16; OUT = bf16 hi/lo pair,
// with Q columns (col < D_) pre-scaled by 0.125 before the split.
// ---------------------------------------------------------------------------
__global__ __launch_bounds__(256, 2) void gemm_a32_obf(
    const float* __restrict__ A,
    const __nv_bfloat16* __restrict__ Bthi,
    const __nv_bfloat16* __restrict__ Btlo,
    const float* __restrict__ bias,
    __nv_bfloat16* __restrict__ Ohi, __nv_bfloat16* __restrict__ Olo,
    int M, int Ntot, int K)
{
    extern __shared__ __align__(1024) uint8_t smem[];
    const uint32_t sb  = smem_u32(smem);
    const uint32_t Ahi = sb, Alo = sb + 16384, Bhi = sb + 32768, Blo = sb + 49152;

    const int tid  = threadIdx.x;
    const int lane = tid & 31;
    const int wid  = tid >> 5;
    const int wm   = wid & 1;
    const int wn   = wid >> 1;
    const int m0   = blockIdx.y << 7;
    const int n0   = blockIdx.x << 7;

    float acc[4][4][4];
#pragma unroll
    for (int mt = 0; mt < 4; mt++)
#pragma unroll
        for (int nt = 0; nt < 4; nt++)
#pragma unroll
            for (int e = 0; e < 4; e++) acc[mt][nt][e] = 0.f;

    const int aRow = lane & 15;
    const int aKs  = lane >> 4;
    const int bRow = lane & 7;
    const int bKs  = (lane >> 3) & 1;

    const int nchunks = K >> 6;
    for (int c = 0; c < nchunks; c++) {
        const int k0 = c << 6;
        __syncthreads();

#pragma unroll
        for (int u = 0; u < 4; u++) {
            int unit = tid + (u << 8);
            int r = unit >> 3, g = unit & 7;
            uint32_t off = SWZOFF(r, g);
            cp_async16(Bhi + off, Bthi + (size_t)(n0 + r) * K + k0 + (g << 3));
            cp_async16(Blo + off, Btlo + (size_t)(n0 + r) * K + k0 + (g << 3));
        }
        cp_commit();

#pragma unroll
        for (int u = 0; u < 4; u++) {
            int unit = tid + (u << 8);
            int r = unit >> 3, g = unit & 7;
            const float* ap = A + (size_t)(m0 + r) * K + k0 + (g << 3);
            float4 v0 = *(const float4*)ap;
            float4 v1 = *(const float4*)(ap + 4);
            float f[8] = {v0.x, v0.y, v0.z, v0.w, v1.x, v1.y, v1.z, v1.w};
            float l[8];
#pragma unroll
            for (int e = 0; e < 8; e++) {
                __nv_bfloat16 h = __float2bfloat16(f[e]);
                l[e] = f[e] - __bfloat162float(h);
            }
            uint4 hp, lp;
            hp.x = pack_bf2(f[0], f[1]); hp.y = pack_bf2(f[2], f[3]);
            hp.z = pack_bf2(f[4], f[5]); hp.w = pack_bf2(f[6], f[7]);
            lp.x = pack_bf2(l[0], l[1]); lp.y = pack_bf2(l[2], l[3]);
            lp.z = pack_bf2(l[4], l[5]); lp.w = pack_bf2(l[6], l[7]);
            uint32_t off = SWZOFF(r, g);
            *(uint4*)(smem + off)         = hp;
            *(uint4*)(smem + 16384 + off) = lp;
        }
        cp_wait0();
        __syncthreads();

#pragma unroll
        for (int ks = 0; ks < 4; ks++) {
            const int kc = ks << 1;
            uint32_t ah[4][4], al[4][4];
#pragma unroll
            for (int mt = 0; mt < 4; mt++) {
                int row = (wm << 6) + (mt << 4) + aRow;
                uint32_t off = SWZOFF(row, kc + aKs);
                ldm4(ah[mt], Ahi + off);
                ldm4(al[mt], Alo + off);
            }
            uint32_t bh[4][2], bl[4][2];
#pragma unroll
            for (int nt = 0; nt < 4; nt++) {
                int row = (wn << 5) + (nt << 3) + bRow;
                uint32_t off = SWZOFF(row, kc + bKs);
                ldm2(bh[nt], Bhi + off);
                ldm2(bl[nt], Blo + off);
            }
#pragma unroll
            for (int mt = 0; mt < 4; mt++)
#pragma unroll
                for (int nt = 0; nt < 4; nt++) {
                    mma16816(acc[mt][nt], ah[mt], bh[nt]);
                    mma16816(acc[mt][nt], al[mt], bh[nt]);
                    mma16816(acc[mt][nt], ah[mt], bl[nt]);
                }
        }
    }

    // epilogue: bias, optional Q-scale, bf16 hi/lo split, store
#pragma unroll
    for (int mt = 0; mt < 4; mt++) {
        int row = m0 + (wm << 6) + (mt << 4) + (lane >> 2);
#pragma unroll
        for (int nt = 0; nt < 4; nt++) {
            int col = n0 + (wn << 5) + (nt << 3) + ((lane & 3) << 1);
            float2 bv = *(const float2*)&bias[col];
            float sc = (col < D_) ? 0.125f : 1.0f;   // scale Q part (exact)
            float x0 = (acc[mt][nt][0] + bv.x) * sc;
            float y0 = (acc[mt][nt][1] + bv.y) * sc;
            float x1 = (acc[mt][nt][2] + bv.x) * sc;
            float y1 = (acc[mt][nt][3] + bv.y) * sc;
            uint32_t h0, l0, h1, l1;
            split2(x0, y0, h0, l0);
            split2(x1, y1, h1, l1);
            size_t i0 = (size_t)row * Ntot + col;
            size_t i1 = (size_t)(row + 8) * Ntot + col;
            *(uint32_t*)&Ohi[i0] = h0;  *(uint32_t*)&Olo[i0] = l0;
            *(uint32_t*)&Ohi[i1] = h1;  *(uint32_t*)&Olo[i1] = l1;
        }
    }
}

// ---------------------------------------------------------------------------
// GEMM-2 (proj): A pre-split bf16 (att), B pre-split bf16; OUT fp32 + bias.
// All staging is pure cp.async.
// ---------------------------------------------------------------------------
__global__ __launch_bounds__(256, 2) void gemm_abf_o32(
    const __nv_bfloat16* __restrict__ Athi,
    const __nv_bfloat16* __restrict__ Atlo,
    const __nv_bfloat16* __restrict__ Bthi,
    const __nv_bfloat16* __restrict__ Btlo,
    const float* __restrict__ bias, float* __restrict__ C,
    int M, int Ntot, int K)
{
    extern __shared__ __align__(1024) uint8_t smem[];
    const uint32_t sb  = smem_u32(smem);
    const uint32_t Ahi = sb, Alo = sb + 16384, Bhi = sb + 32768, Blo = sb + 49152;

    const int tid  = threadIdx.x;
    const int lane = tid & 31;
    const int wid  = tid >> 5;
    const int wm   = wid & 1;
    const int wn   = wid >> 1;
    const int m0   = blockIdx.y << 7;
    const int n0   = blockIdx.x << 7;

    float acc[4][4][4];
#pragma unroll
    for (int mt = 0; mt < 4; mt++)
#pragma unroll
        for (int nt = 0; nt < 4; nt++)
#pragma unroll
            for (int e = 0; e < 4; e++) acc[mt][nt][e] = 0.f;

    const int aRow = lane & 15;
    const int aKs  = lane >> 4;
    const int bRow = lane & 7;
    const int bKs  = (lane >> 3) & 1;

    const int nchunks = K >> 6;
    for (int c = 0; c < nchunks; c++) {
        const int k0 = c << 6;
        __syncthreads();

#pragma unroll
        for (int u = 0; u < 4; u++) {
            int unit = tid + (u << 8);
            int r = unit >> 3, g = unit & 7;
            uint32_t off = SWZOFF(r, g);
            cp_async16(Ahi + off, Athi + (size_t)(m0 + r) * K + k0 + (g << 3));
            cp_async16(Alo + off, Atlo + (size_t)(m0 + r) * K + k0 + (g << 3));
            cp_async16(Bhi + off, Bthi + (size_t)(n0 + r) * K + k0 + (g << 3));
            cp_async16(Blo + off, Btlo + (size_t)(n0 + r) * K + k0 + (g << 3));
        }
        cp_commit();
        cp_wait0();
        __syncthreads();

#pragma unroll
        for (int ks = 0; ks < 4; ks++) {
            const int kc = ks << 1;
            uint32_t ah[4][4], al[4][4];
#pragma unroll
            for (int mt = 0; mt < 4; mt++) {
                int row = (wm << 6) + (mt << 4) + aRow;
                uint32_t off = SWZOFF(row, kc + aKs);
                ldm4(ah[mt], Ahi + off);
                ldm4(al[mt], Alo + off);
            }
            uint32_t bh[4][2], bl[4][2];
#pragma unroll
            for (int nt = 0; nt < 4; nt++) {
                int row = (wn << 5) + (nt << 3) + bRow;
                uint32_t off = SWZOFF(row, kc + bKs);
                ldm2(bh[nt], Bhi + off);
                ldm2(bl[nt], Blo + off);
            }
#pragma unroll
            for (int mt = 0; mt < 4; mt++)
#pragma unroll
                for (int nt = 0; nt < 4; nt++) {
                    mma16816(acc[mt][nt], ah[mt], bh[nt]);
                    mma16816(acc[mt][nt], al[mt], bh[nt]);
                    mma16816(acc[mt][nt], ah[mt], bl[nt]);
                }
        }
    }

#pragma unroll
    for (int mt = 0; mt < 4; mt++) {
        int row = m0 + (wm << 6) + (mt << 4) + (lane >> 2);
#pragma unroll
        for (int nt = 0; nt < 4; nt++) {
            int col = n0 + (wn << 5) + (nt << 3) + ((lane & 3) << 1);
            float2 bv = *(const float2*)&bias[col];
            float2 o0, o1;
            o0.x = acc[mt][nt][0] + bv.x;
            o0.y = acc[mt][nt][1] + bv.y;
            o1.x = acc[mt][nt][2] + bv.x;
            o1.y = acc[mt][nt][3] + bv.y;
            *(float2*)&C[(size_t)row * Ntot + col]       = o0;
            *(float2*)&C[(size_t)(row + 8) * Ntot + col] = o1;
        }
    }
}

// ---------------------------------------------------------------------------
// Flash attention on tensor cores (mma.sync bf16x3), causal.
// All inputs pre-split bf16 -> staging is pure cp.async (no conversion).
// SMEM union 32KB: prologue Q hi/lo; mainloop K/V hi/lo. 2 CTAs/SM.
// Output written as bf16 hi/lo for the proj GEMM.
// ---------------------------------------------------------------------------
__global__ __launch_bounds__(256, 2) void flash_attn_mma(
    const __nv_bfloat16* __restrict__ qkv_hi,
    const __nv_bfloat16* __restrict__ qkv_lo,
    __nv_bfloat16* __restrict__ att_hi,
    __nv_bfloat16* __restrict__ att_lo)
{
    extern __shared__ __align__(1024) uint8_t sm[];
    const uint32_t sb  = smem_u32(sm);
    const uint32_t Qhi = sb,          Qlo = sb + 16384;
    const uint32_t Khi = sb,          Klo = sb + 8192;
    const uint32_t Vhi = sb + 16384,  Vlo = sb + 24576;

    const int tid  = threadIdx.x;
    const int lane = tid & 31;
    const int wid  = tid >> 5;
    const int mblk = (int)gridDim.x - 1 - (int)blockIdx.x;  // heavy first
    const int h    = blockIdx.y;
    const int b    = blockIdx.z;
    const int m0   = mblk << 7;

    const size_t rowbase = (size_t)b * S_ * QKVLD + h * DH_;
    const __nv_bfloat16* Qh = qkv_hi + rowbase;
    const __nv_bfloat16* Ql = qkv_lo + rowbase;
    const __nv_bfloat16* Kh = Qh + D_;
    const __nv_bfloat16* Kl = Ql + D_;
    const __nv_bfloat16* Vh = Qh + 2 * D_;
    const __nv_bfloat16* Vl = Ql + 2 * D_;

    // ---- stage Q via cp.async (Q already scaled by 0.125 upstream) ----
#pragma unroll
    for (int u = 0; u < 4; u++) {
        int unit = tid + (u << 8);
        int r = unit >> 3, g = unit & 7;
        uint32_t off = SWZOFF(r, g);
        cp_async16(Qhi + off, Qh + (size_t)(m0 + r) * QKVLD + (g << 3));
        cp_async16(Qlo + off, Ql + (size_t)(m0 + r) * QKVLD + (g << 3));
    }
    cp_commit();
    cp_wait0();
    __syncthreads();

    // ---- Q fragments (register-resident for the whole CTA) ----
    uint32_t qh[4][4], ql[4][4];
    const int aRow = lane & 15;
    const int aKs  = lane >> 4;
#pragma unroll
    for (int ks = 0; ks < 4; ks++) {
        uint32_t off = SWZOFF((wid << 4) + aRow, (ks << 1) + aKs);
        ldm4(qh[ks], Qhi + off);
        ldm4(ql[ks], Qlo + off);
    }

    float o[8][4];
#pragma unroll
    for (int nt = 0; nt < 8; nt++)
#pragma unroll
        for (int e = 0; e < 4; e++) o[nt][e] = 0.f;
    float mrow0 = -1e30f, mrow1 = -1e30f, lrow0 = 0.f, lrow1 = 0.f;

    const int rbase = m0 + (wid << 4) + (lane >> 2);
    const int nkv = 2 * mblk + 2;

    for (int nb = 0; nb < nkv; nb++) {
        const int n0 = nb << 6;
        __syncthreads();   // protect K/V smem (and Q region on first iter)

        // ---- stage K/V hi/lo via cp.async: 4 regions x 2 chunks/thread ----
#pragma unroll
        for (int u = 0; u < 2; u++) {
            int unit = tid + (u << 8);
            int r = unit >> 3, g = unit & 7;
            uint32_t off = SWZOFF(r, g);
            size_t go = (size_t)(n0 + r) * QKVLD + (g << 3);
            cp_async16(Khi + off, Kh + go);
            cp_async16(Klo + off, Kl + go);
            cp_async16(Vhi + off, Vh + go);
            cp_async16(Vlo + off, Vl + go);
        }
        cp_commit();
        cp_wait0();
        __syncthreads();

        // ---- S = QK^T (bf16x3) ----
        float s[8][4];
#pragma unroll
        for (int nt = 0; nt < 8; nt++)
#pragma unroll
            for (int e = 0; e < 4; e++) s[nt][e] = 0.f;

#pragma unroll
        for (int ks = 0; ks < 4; ks++) {
            const uint32_t kc = (ks << 1) + ((lane >> 3) & 1);
#pragma unroll
            for (int nt = 0; nt < 8; nt++) {
                uint32_t off = SWZOFF((nt << 3) + (lane & 7), kc);
                uint32_t bh[2], bl[2];
                ldm2(bh, Khi + off);
                ldm2(bl, Klo + off);
                mma16816(s[nt], qh[ks], bh);
                mma16816(s[nt], ql[ks], bh);
                mma16816(s[nt], qh[ks], bl);
            }
        }

        // ---- causal mask ----
        if (n0 + 63 > m0 + (wid << 4)) {
#pragma unroll
            for (int nt = 0; nt < 8; nt++) {
                int col = n0 + (nt << 3) + ((lane & 3) << 1);
                if (col     > rbase)     s[nt][0] = -1e30f;
                if (col + 1 > rbase)     s[nt][1] = -1e30f;
                if (col     > rbase + 8) s[nt][2] = -1e30f;
                if (col + 1 > rbase + 8) s[nt][3] = -1e30f;
            }
        }

        // ---- online softmax ----
        float mx0 = s[0][0], mx1 = s[0][2];
#pragma unroll
        for (int nt = 0; nt < 8; nt++) {
            mx0 = fmaxf(mx0, fmaxf(s[nt][0], s[nt][1]));
            mx1 = fmaxf(mx1, fmaxf(s[nt][2], s[nt][3]));
        }
        mx0 = fmaxf(mx0, __shfl_xor_sync(0xffffffffu, mx0, 1));
        mx0 = fmaxf(mx0, __shfl_xor_sync(0xffffffffu, mx0, 2));
        mx1 = fmaxf(mx1, __shfl_xor_sync(0xffffffffu, mx1, 1));
        mx1 = fmaxf(mx1, __shfl_xor_sync(0xffffffffu, mx1, 2));

        float mn0 = fmaxf(mrow0, mx0);
        float mn1 = fmaxf(mrow1, mx1);
        float al0 = __expf(mrow0 - mn0);
        float al1 = __expf(mrow1 - mn1);
        mrow0 = mn0; mrow1 = mn1;

        float rs0 = 0.f, rs1 = 0.f;
#pragma unroll
        for (int nt = 0; nt < 8; nt++) {
            s[nt][0] = __expf(s[nt][0] - mn0);
            s[nt][1] = __expf(s[nt][1] - mn0);
            s[nt][2] = __expf(s[nt][2] - mn1);
            s[nt][3] = __expf(s[nt][3] - mn1);
            rs0 += s[nt][0] + s[nt][1];
            rs1 += s[nt][2] + s[nt][3];
        }
        rs0 += __shfl_xor_sync(0xffffffffu, rs0, 1);
        rs0 += __shfl_xor_sync(0xffffffffu, rs0, 2);
        rs1 += __shfl_xor_sync(0xffffffffu, rs1, 1);
        rs1 += __shfl_xor_sync(0xffffffffu, rs1, 2);
        lrow0 = lrow0 * al0 + rs0;
        lrow1 = lrow1 * al1 + rs1;

#pragma unroll
        for (int nt = 0; nt < 8; nt++) {
            o[nt][0] *= al0; o[nt][1] *= al0;
            o[nt][2] *= al1; o[nt][3] *= al1;
        }

        // ---- O += P @ V (bf16x3) ----
#pragma unroll
        for (int ks = 0; ks < 4; ks++) {
            uint32_t pa[4], pl[4];
            split2(s[2*ks][0],   s[2*ks][1],   pa[0], pl[0]);
            split2(s[2*ks][2],   s[2*ks][3],   pa[1], pl[1]);
            split2(s[2*ks+1][0], s[2*ks+1][1], pa[2], pl[2]);
            split2(s[2*ks+1][2], s[2*ks+1][3], pa[3], pl[3]);
            const uint32_t vrow = (ks << 4) + (lane & 15);
#pragma unroll
            for (int nt = 0; nt < 8; nt++) {
                uint32_t off = SWZOFF(vrow, nt);
                uint32_t vh[2], vl[2];
                ldm2t(vh, Vhi + off);
                ldm2t(vl, Vlo + off);
                mma16816(o[nt], pa, vh);
                mma16816(o[nt], pl, vh);
                mma16816(o[nt], pa, vl);
            }
        }
    }

    // ---- epilogue: normalize, split to bf16 hi/lo, store ----
    float inv0 = 1.0f / lrow0;
    float inv1 = 1.0f / lrow1;
    int r0 = m0 + (wid << 4) + (lane >> 2);
#pragma unroll
    for (int nt = 0; nt < 8; nt++) {
        int col = h * DH_ + (nt << 3) + ((lane & 3) << 1);
        uint32_t h0, l0, h1, l1;
        split2(o[nt][0] * inv0, o[nt][1] * inv0, h0, l0);
        split2(o[nt][2] * inv1, o[nt][3] * inv1, h1, l1);
        size_t i0 = ((size_t)b * S_ + r0) * D_ + col;
        size_t i1 = ((size_t)b * S_ + r0 + 8) * D_ + col;
        *(uint32_t*)&att_hi[i0] = h0;  *(uint32_t*)&att_lo[i0] = l0;
        *(uint32_t*)&att_hi[i1] = h1;  *(uint32_t*)&att_lo[i1] = l1;
    }
}

// ---------------------------------------------------------------------------
extern "C" void kernel_launch(void* const* d_in, const int* in_sizes, int n_in,
                              void* d_out, int out_size)
{
    (void)in_sizes; (void)n_in; (void)out_size;
    const float* x    = (const float*)d_in[0];
    const float* Wqkv = (const float*)d_in[2];
    const float* bqkv = (const float*)d_in[3];
    const float* Wp   = (const float*)d_in[4];
    const float* bp   = (const float*)d_in[5];
    float* out = (float*)d_out;

    __nv_bfloat16 *qh, *ql, *ah, *al, *wqh, *wql, *wph, *wpl;
    cudaGetSymbolAddress((void**)&qh,  g_qkv_hi);
    cudaGetSymbolAddress((void**)&ql,  g_qkv_lo);
    cudaGetSymbolAddress((void**)&ah,  g_att_hi);
    cudaGetSymbolAddress((void**)&al,  g_att_lo);
    cudaGetSymbolAddress((void**)&wqh, g_wqkvT_hi);
    cudaGetSymbolAddress((void**)&wql, g_wqkvT_lo);
    cudaGetSymbolAddress((void**)&wph, g_wpT_hi);
    cudaGetSymbolAddress((void**)&wpl, g_wpT_lo);

    cudaFuncSetAttribute(gemm_a32_obf, cudaFuncAttributeMaxDynamicSharedMemorySize, 65536);
    cudaFuncSetAttribute(gemm_abf_o32, cudaFuncAttributeMaxDynamicSharedMemorySize, 65536);
    cudaFuncSetAttribute(flash_attn_mma, cudaFuncAttributeMaxDynamicSharedMemorySize, 32768);

    // Transpose + split weights (bf16 hi/lo)
    wtrans<<<dim3(QKVLD / 32, D_ / 32), dim3(32, 8)>>>(Wqkv, wqh, wql, D_, QKVLD);
    wtrans<<<dim3(D_ / 32, D_ / 32),   dim3(32, 8)>>>(Wp,   wph, wpl, D_, D_);

    const int M = M_TOT;

    // QKV projection -> pre-split bf16 (Q scaled by 0.125)
    gemm_a32_obf<<<dim3(QKVLD / 128, M / 128), 256, 65536>>>(
        x, wqh, wql, bqkv, qh, ql, M, QKVLD, D_);

    // Causal flash attention (pure cp.async staging) -> pre-split bf16
    flash_attn_mma<<<dim3(S_ / 128, H_, B_), 256, 32768>>>(qh, ql, ah, al);

    // Output projection (all-bf16 staging) -> fp32 out
    gemm_abf_o32<<<dim3(D_ / 128, M / 128), 256, 65536>>>(
        ah, al, wph, wpl, bp, out, M, D_, D_);
}

// round 13
// speedup vs baseline: 4.8089x; 1.0344x over previous
#include <cuda_runtime.h>
#include <cuda_bf16.h>
#include <cstdint>

#define B_   2
#define S_   2048
#define D_   768
#define H_   12
#define DH_  64
#define QKVLD (3 * D_)   // 2304
#define M_TOT (B_ * S_)  // 4096

// ---------------------------------------------------------------------------
// Scratch (allocation-free rule: __device__ globals)
// All intermediates are bf16 hi/lo pairs (value = hi + lo, err ~2^-16).
// ---------------------------------------------------------------------------
__device__ __nv_bfloat16 g_x_hi[(size_t)M_TOT * D_];      // x split
__device__ __nv_bfloat16 g_x_lo[(size_t)M_TOT * D_];
__device__ __nv_bfloat16 g_qkv_hi[(size_t)M_TOT * QKVLD]; // Q pre-scaled x0.125
__device__ __nv_bfloat16 g_qkv_lo[(size_t)M_TOT * QKVLD];
__device__ __nv_bfloat16 g_att_hi[(size_t)M_TOT * D_];
__device__ __nv_bfloat16 g_att_lo[(size_t)M_TOT * D_];
__device__ __nv_bfloat16 g_wqkvT_hi[(size_t)QKVLD * D_];  // W_qkv^T [2304,768]
__device__ __nv_bfloat16 g_wqkvT_lo[(size_t)QKVLD * D_];
__device__ __nv_bfloat16 g_wpT_hi[(size_t)D_ * D_];       // W_proj^T [768,768]
__device__ __nv_bfloat16 g_wpT_lo[(size_t)D_ * D_];

// ---------------------------------------------------------------------------
// sm_80-level building blocks (compile clean for compute_103)
// ---------------------------------------------------------------------------
__device__ __forceinline__ uint32_t smem_u32(const void* p) {
    uint32_t a;
    asm("{ .reg .u64 t; cvta.to.shared.u64 t, %1; cvt.u32.u64 %0, t; }" : "=r"(a) : "l"(p));
    return a;
}
__device__ __forceinline__ void cp_async16(uint32_t dst, const void* src) {
    asm volatile("cp.async.cg.shared.global [%0], [%1], 16;" :: "r"(dst), "l"(src));
}
__device__ __forceinline__ void cp_commit() { asm volatile("cp.async.commit_group;"); }
__device__ __forceinline__ void cp_wait0()  { asm volatile("cp.async.wait_group 0;"); }
__device__ __forceinline__ void cp_wait1()  { asm volatile("cp.async.wait_group 1;"); }

__device__ __forceinline__ void ldm4(uint32_t* r, uint32_t addr) {
    asm volatile("ldmatrix.sync.aligned.m8n8.x4.shared.b16 {%0,%1,%2,%3}, [%4];"
        : "=r"(r[0]), "=r"(r[1]), "=r"(r[2]), "=r"(r[3]) : "r"(addr));
}
__device__ __forceinline__ void ldm2(uint32_t* r, uint32_t addr) {
    asm volatile("ldmatrix.sync.aligned.m8n8.x2.shared.b16 {%0,%1}, [%2];"
        : "=r"(r[0]), "=r"(r[1]) : "r"(addr));
}
__device__ __forceinline__ void ldm2t(uint32_t* r, uint32_t addr) {
    asm volatile("ldmatrix.sync.aligned.m8n8.x2.trans.shared.b16 {%0,%1}, [%2];"
        : "=r"(r[0]), "=r"(r[1]) : "r"(addr));
}
__device__ __forceinline__ void mma16816(float* d, const uint32_t* a, const uint32_t* b) {
    asm volatile(
        "mma.sync.aligned.m16n8k16.row.col.f32.bf16.bf16.f32 "
        "{%0,%1,%2,%3}, {%4,%5,%6,%7}, {%8,%9}, {%0,%1,%2,%3};"
        : "+f"(d[0]), "+f"(d[1]), "+f"(d[2]), "+f"(d[3])
        : "r"(a[0]), "r"(a[1]), "r"(a[2]), "r"(a[3]), "r"(b[0]), "r"(b[1]));
}
__device__ __forceinline__ uint32_t pack_bf2(float a, float b) {
    __nv_bfloat162 t = __floats2bfloat162_rn(a, b);
    return *reinterpret_cast<uint32_t*>(&t);
}
__device__ __forceinline__ void split2(float x, float y, uint32_t& hi, uint32_t& lo) {
    __nv_bfloat16 hx = __float2bfloat16(x);
    __nv_bfloat16 hy = __float2bfloat16(y);
    hi = pack_bf2(x, y);
    lo = pack_bf2(x - __bfloat162float(hx), y - __bfloat162float(hy));
}

#define SWZOFF(r, g) (((uint32_t)(r) << 7) + (((uint32_t)((g) ^ ((r) & 7))) << 4))

// ---------------------------------------------------------------------------
// x split: fp32 -> bf16 hi/lo (elementwise)
// ---------------------------------------------------------------------------
__global__ __launch_bounds__(256) void xsplit(
    const float* __restrict__ X,
    __nv_bfloat16* __restrict__ Xhi, __nv_bfloat16* __restrict__ Xlo)
{
    size_t i = ((size_t)blockIdx.x * 256 + threadIdx.x) << 2;
    float4 v = *(const float4*)(X + i);
    uint32_t h0, l0, h1, l1;
    split2(v.x, v.y, h0, l0);
    split2(v.z, v.w, h1, l1);
    uint2 hp = make_uint2(h0, h1);
    uint2 lp = make_uint2(l0, l1);
    *(uint2*)&Xhi[i] = hp;
    *(uint2*)&Xlo[i] = lp;
}

// ---------------------------------------------------------------------------
// Weight transpose + bf16 hi/lo split: W[K,N] -> T{hi,lo}[N,K]
// ---------------------------------------------------------------------------
__global__ void wtrans(const float* __restrict__ W,
                       __nv_bfloat16* __restrict__ Thi,
                       __nv_bfloat16* __restrict__ Tlo, int K, int N)
{
    __shared__ float t[32][33];
    int bx = blockIdx.x << 5;
    int by = blockIdx.y << 5;
    int tx = threadIdx.x, ty = threadIdx.y;
#pragma unroll
    for (int j = 0; j < 4; j++)
        t[ty + j * 8][tx] = W[(size_t)(by + ty + j * 8) * N + bx + tx];
    __syncthreads();
#pragma unroll
    for (int j = 0; j < 4; j++) {
        float v = t[tx][ty + j * 8];
        __nv_bfloat16 hi = __float2bfloat16(v);
        float lo = v - __bfloat162float(hi);
        size_t o = (size_t)(bx + ty + j * 8) * K + by + tx;
        Thi[o] = hi;
        Tlo[o] = __float2bfloat16(lo);
    }
}

// ---------------------------------------------------------------------------
// Shared GEMM mainloop skeleton (A,B pre-split bf16, all cp.async staging).
// Two epilogue variants below.
// ---------------------------------------------------------------------------
#define GEMM_MAINLOOP()                                                        \
    float acc[4][4][4];                                                        \
    _Pragma("unroll")                                                          \
    for (int mt = 0; mt < 4; mt++)                                             \
        _Pragma("unroll")                                                      \
        for (int nt = 0; nt < 4; nt++)                                         \
            _Pragma("unroll")                                                  \
            for (int e = 0; e < 4; e++) acc[mt][nt][e] = 0.f;                  \
    const int aRow = lane & 15;                                                \
    const int aKs  = lane >> 4;                                                \
    const int bRow = lane & 7;                                                 \
    const int bKs  = (lane >> 3) & 1;                                          \
    const int nchunks = K >> 6;                                                \
    for (int c = 0; c < nchunks; c++) {                                        \
        const int k0 = c << 6;                                                 \
        __syncthreads();                                                       \
        _Pragma("unroll")                                                      \
        for (int u = 0; u < 4; u++) {                                          \
            int unit = tid + (u << 8);                                         \
            int r = unit >> 3, g = unit & 7;                                   \
            uint32_t off = SWZOFF(r, g);                                       \
            cp_async16(Ahi + off, Athi + (size_t)(m0 + r) * K + k0 + (g << 3));\
            cp_async16(Alo + off, Atlo + (size_t)(m0 + r) * K + k0 + (g << 3));\
            cp_async16(Bhi + off, Bthi + (size_t)(n0 + r) * K + k0 + (g << 3));\
            cp_async16(Blo + off, Btlo + (size_t)(n0 + r) * K + k0 + (g << 3));\
        }                                                                      \
        cp_commit();                                                           \
        cp_wait0();                                                            \
        __syncthreads();                                                       \
        _Pragma("unroll")                                                      \
        for (int ks = 0; ks < 4; ks++) {                                       \
            const int kc = ks << 1;                                            \
            uint32_t ah[4][4], al[4][4];                                       \
            _Pragma("unroll")                                                  \
            for (int mt = 0; mt < 4; mt++) {                                   \
                int row = (wm << 6) + (mt << 4) + aRow;                        \
                uint32_t off = SWZOFF(row, kc + aKs);                          \
                ldm4(ah[mt], Ahi + off);                                       \
                ldm4(al[mt], Alo + off);                                       \
            }                                                                  \
            uint32_t bh[4][2], bl[4][2];                                       \
            _Pragma("unroll")                                                  \
            for (int nt = 0; nt < 4; nt++) {                                   \
                int row = (wn << 5) + (nt << 3) + bRow;                        \
                uint32_t off = SWZOFF(row, kc + bKs);                          \
                ldm2(bh[nt], Bhi + off);                                       \
                ldm2(bl[nt], Blo + off);                                       \
            }                                                                  \
            _Pragma("unroll")                                                  \
            for (int mt = 0; mt < 4; mt++)                                     \
                _Pragma("unroll")                                              \
                for (int nt = 0; nt < 4; nt++) {                               \
                    mma16816(acc[mt][nt], ah[mt], bh[nt]);                     \
                    mma16816(acc[mt][nt], al[mt], bh[nt]);                     \
                    mma16816(acc[mt][nt], ah[mt], bl[nt]);                     \
                }                                                              \
        }                                                                      \
    }

// GEMM variant 1: output = bf16 hi/lo split, Q columns scaled by 0.125
__global__ __launch_bounds__(256, 2) void gemm_abf_obf(
    const __nv_bfloat16* __restrict__ Athi,
    const __nv_bfloat16* __restrict__ Atlo,
    const __nv_bfloat16* __restrict__ Bthi,
    const __nv_bfloat16* __restrict__ Btlo,
    const float* __restrict__ bias,
    __nv_bfloat16* __restrict__ Ohi, __nv_bfloat16* __restrict__ Olo,
    int M, int Ntot, int K)
{
    extern __shared__ __align__(1024) uint8_t smem[];
    const uint32_t sb  = smem_u32(smem);
    const uint32_t Ahi = sb, Alo = sb + 16384, Bhi = sb + 32768, Blo = sb + 49152;
    const int tid  = threadIdx.x;
    const int lane = tid & 31;
    const int wid  = tid >> 5;
    const int wm   = wid & 1;
    const int wn   = wid >> 1;
    const int m0   = blockIdx.y << 7;
    const int n0   = blockIdx.x << 7;

    GEMM_MAINLOOP()

#pragma unroll
    for (int mt = 0; mt < 4; mt++) {
        int row = m0 + (wm << 6) + (mt << 4) + (lane >> 2);
#pragma unroll
        for (int nt = 0; nt < 4; nt++) {
            int col = n0 + (wn << 5) + (nt << 3) + ((lane & 3) << 1);
            float2 bv = *(const float2*)&bias[col];
            float sc = (col < D_) ? 0.125f : 1.0f;   // scale Q part (exact)
            float x0 = (acc[mt][nt][0] + bv.x) * sc;
            float y0 = (acc[mt][nt][1] + bv.y) * sc;
            float x1 = (acc[mt][nt][2] + bv.x) * sc;
            float y1 = (acc[mt][nt][3] + bv.y) * sc;
            uint32_t h0, l0, h1, l1;
            split2(x0, y0, h0, l0);
            split2(x1, y1, h1, l1);
            size_t i0 = (size_t)row * Ntot + col;
            size_t i1 = (size_t)(row + 8) * Ntot + col;
            *(uint32_t*)&Ohi[i0] = h0;  *(uint32_t*)&Olo[i0] = l0;
            *(uint32_t*)&Ohi[i1] = h1;  *(uint32_t*)&Olo[i1] = l1;
        }
    }
}

// GEMM variant 2: output fp32 + bias (final projection)
__global__ __launch_bounds__(256, 2) void gemm_abf_o32(
    const __nv_bfloat16* __restrict__ Athi,
    const __nv_bfloat16* __restrict__ Atlo,
    const __nv_bfloat16* __restrict__ Bthi,
    const __nv_bfloat16* __restrict__ Btlo,
    const float* __restrict__ bias, float* __restrict__ C,
    int M, int Ntot, int K)
{
    extern __shared__ __align__(1024) uint8_t smem[];
    const uint32_t sb  = smem_u32(smem);
    const uint32_t Ahi = sb, Alo = sb + 16384, Bhi = sb + 32768, Blo = sb + 49152;
    const int tid  = threadIdx.x;
    const int lane = tid & 31;
    const int wid  = tid >> 5;
    const int wm   = wid & 1;
    const int wn   = wid >> 1;
    const int m0   = blockIdx.y << 7;
    const int n0   = blockIdx.x << 7;

    GEMM_MAINLOOP()

#pragma unroll
    for (int mt = 0; mt < 4; mt++) {
        int row = m0 + (wm << 6) + (mt << 4) + (lane >> 2);
#pragma unroll
        for (int nt = 0; nt < 4; nt++) {
            int col = n0 + (wn << 5) + (nt << 3) + ((lane & 3) << 1);
            float2 bv = *(const float2*)&bias[col];
            float2 o0, o1;
            o0.x = acc[mt][nt][0] + bv.x;
            o0.y = acc[mt][nt][1] + bv.y;
            o1.x = acc[mt][nt][2] + bv.x;
            o1.y = acc[mt][nt][3] + bv.y;
            *(float2*)&C[(size_t)row * Ntot + col]       = o0;
            *(float2*)&C[(size_t)(row + 8) * Ntot + col] = o1;
        }
    }
}

// ---------------------------------------------------------------------------
// Flash attention (mma.sync bf16x3), causal, DOUBLE-BUFFERED K/V pipeline.
// 2 x 32KB buffers (Khi/Klo/Vhi/Vlo each 8KB). Tile t -> buf[t&1].
// Per iter: wait_group 1 (tile nb ready; nb+1 in flight), compute, sync,
// issue tile nb+2 into the just-freed buffer. One commit per iteration.
// 64KB smem, 2 CTAs/SM.
// ---------------------------------------------------------------------------
__global__ __launch_bounds__(256, 2) void flash_attn_mma(
    const __nv_bfloat16* __restrict__ qkv_hi,
    const __nv_bfloat16* __restrict__ qkv_lo,
    __nv_bfloat16* __restrict__ att_hi,
    __nv_bfloat16* __restrict__ att_lo)
{
    extern __shared__ __align__(1024) uint8_t sm[];
    const uint32_t sb = smem_u32(sm);
    // prologue: Q hi at sb, Q lo at sb+16384 (inside buffer 0+part of 1)

    const int tid  = threadIdx.x;
    const int lane = tid & 31;
    const int wid  = tid >> 5;
    const int mblk = (int)gridDim.x - 1 - (int)blockIdx.x;  // heavy first
    const int h    = blockIdx.y;
    const int b    = blockIdx.z;
    const int m0   = mblk << 7;

    const size_t rowbase = (size_t)b * S_ * QKVLD + h * DH_;
    const __nv_bfloat16* Qh = qkv_hi + rowbase;
    const __nv_bfloat16* Ql = qkv_lo + rowbase;
    const __nv_bfloat16* Kh = Qh + D_;
    const __nv_bfloat16* Kl = Ql + D_;
    const __nv_bfloat16* Vh = Qh + 2 * D_;
    const __nv_bfloat16* Vl = Ql + 2 * D_;

    // ---- stage Q via cp.async (group 0) ----
#pragma unroll
    for (int u = 0; u < 4; u++) {
        int unit = tid + (u << 8);
        int r = unit >> 3, g = unit & 7;
        uint32_t off = SWZOFF(r, g);
        cp_async16(sb + off,         Qh + (size_t)(m0 + r) * QKVLD + (g << 3));
        cp_async16(sb + 16384 + off, Ql + (size_t)(m0 + r) * QKVLD + (g << 3));
    }
    cp_commit();
    cp_wait0();
    __syncthreads();

    // ---- Q fragments (register-resident) ----
    uint32_t qh[4][4], ql[4][4];
    const int aRow = lane & 15;
    const int aKs  = lane >> 4;
#pragma unroll
    for (int ks = 0; ks < 4; ks++) {
        uint32_t off = SWZOFF((wid << 4) + aRow, (ks << 1) + aKs);
        ldm4(qh[ks], sb + off);
        ldm4(ql[ks], sb + 16384 + off);
    }
    __syncthreads();   // Q reads done before tile 0 overwrites buffer 0

    const int rbase = m0 + (wid << 4) + (lane >> 2);
    const int nkv = 2 * mblk + 2;

    // ---- prologue issues: tile 0 (group 1), tile 1 (group 2) ----
    {
        // tile 0 -> buf 0
        const int n0 = 0;
#pragma unroll
        for (int u = 0; u < 2; u++) {
            int unit = tid + (u << 8);
            int r = unit >> 3, g = unit & 7;
            uint32_t off = SWZOFF(r, g);
            size_t go = (size_t)(n0 + r) * QKVLD + (g << 3);
            cp_async16(sb + off,         Kh + go);
            cp_async16(sb + 8192 + off,  Kl + go);
            cp_async16(sb + 16384 + off, Vh + go);
            cp_async16(sb + 24576 + off, Vl + go);
        }
        cp_commit();
        if (nkv > 1) {
            const int n1 = 64;
#pragma unroll
            for (int u = 0; u < 2; u++) {
                int unit = tid + (u << 8);
                int r = unit >> 3, g = unit & 7;
                uint32_t off = SWZOFF(r, g);
                size_t go = (size_t)(n1 + r) * QKVLD + (g << 3);
                cp_async16(sb + 32768 + off, Kh + go);
                cp_async16(sb + 40960 + off, Kl + go);
                cp_async16(sb + 49152 + off, Vh + go);
                cp_async16(sb + 57344 + off, Vl + go);
            }
        }
        cp_commit();   // commit even if empty (group accounting)
    }

    float o[8][4];
#pragma unroll
    for (int nt = 0; nt < 8; nt++)
#pragma unroll
        for (int e = 0; e < 4; e++) o[nt][e] = 0.f;
    float mrow0 = -1e30f, mrow1 = -1e30f, lrow0 = 0.f, lrow1 = 0.f;

    for (int nb = 0; nb < nkv; nb++) {
        const int n0 = nb << 6;
        const uint32_t bufb = sb + (uint32_t)(nb & 1) * 32768u;
        const uint32_t Khi = bufb, Klo = bufb + 8192;
        const uint32_t Vhi = bufb + 16384, Vlo = bufb + 24576;

        cp_wait1();        // tile nb resident (tile nb+1 may be in flight)
        __syncthreads();

        // ---- S = QK^T (bf16x3) ----
        float s[8][4];
#pragma unroll
        for (int nt = 0; nt < 8; nt++)
#pragma unroll
            for (int e = 0; e < 4; e++) s[nt][e] = 0.f;

#pragma unroll
        for (int ks = 0; ks < 4; ks++) {
            const uint32_t kc = (ks << 1) + ((lane >> 3) & 1);
#pragma unroll
            for (int nt = 0; nt < 8; nt++) {
                uint32_t off = SWZOFF((nt << 3) + (lane & 7), kc);
                uint32_t bh[2], bl[2];
                ldm2(bh, Khi + off);
                ldm2(bl, Klo + off);
                mma16816(s[nt], qh[ks], bh);
                mma16816(s[nt], ql[ks], bh);
                mma16816(s[nt], qh[ks], bl);
            }
        }

        // ---- causal mask ----
        if (n0 + 63 > m0 + (wid << 4)) {
#pragma unroll
            for (int nt = 0; nt < 8; nt++) {
                int col = n0 + (nt << 3) + ((lane & 3) << 1);
                if (col     > rbase)     s[nt][0] = -1e30f;
                if (col + 1 > rbase)     s[nt][1] = -1e30f;
                if (col     > rbase + 8) s[nt][2] = -1e30f;
                if (col + 1 > rbase + 8) s[nt][3] = -1e30f;
            }
        }

        // ---- online softmax ----
        float mx0 = s[0][0], mx1 = s[0][2];
#pragma unroll
        for (int nt = 0; nt < 8; nt++) {
            mx0 = fmaxf(mx0, fmaxf(s[nt][0], s[nt][1]));
            mx1 = fmaxf(mx1, fmaxf(s[nt][2], s[nt][3]));
        }
        mx0 = fmaxf(mx0, __shfl_xor_sync(0xffffffffu, mx0, 1));
        mx0 = fmaxf(mx0, __shfl_xor_sync(0xffffffffu, mx0, 2));
        mx1 = fmaxf(mx1, __shfl_xor_sync(0xffffffffu, mx1, 1));
        mx1 = fmaxf(mx1, __shfl_xor_sync(0xffffffffu, mx1, 2));

        float mn0 = fmaxf(mrow0, mx0);
        float mn1 = fmaxf(mrow1, mx1);
        float al0 = __expf(mrow0 - mn0);
        float al1 = __expf(mrow1 - mn1);
        mrow0 = mn0; mrow1 = mn1;

        float rs0 = 0.f, rs1 = 0.f;
#pragma unroll
        for (int nt = 0; nt < 8; nt++) {
            s[nt][0] = __expf(s[nt][0] - mn0);
            s[nt][1] = __expf(s[nt][1] - mn0);
            s[nt][2] = __expf(s[nt][2] - mn1);
            s[nt][3] = __expf(s[nt][3] - mn1);
            rs0 += s[nt][0] + s[nt][1];
            rs1 += s[nt][2] + s[nt][3];
        }
        rs0 += __shfl_xor_sync(0xffffffffu, rs0, 1);
        rs0 += __shfl_xor_sync(0xffffffffu, rs0, 2);
        rs1 += __shfl_xor_sync(0xffffffffu, rs1, 1);
        rs1 += __shfl_xor_sync(0xffffffffu, rs1, 2);
        lrow0 = lrow0 * al0 + rs0;
        lrow1 = lrow1 * al1 + rs1;

#pragma unroll
        for (int nt = 0; nt < 8; nt++) {
            o[nt][0] *= al0; o[nt][1] *= al0;
            o[nt][2] *= al1; o[nt][3] *= al1;
        }

        // ---- O += P @ V (bf16x3) ----
#pragma unroll
        for (int ks = 0; ks < 4; ks++) {
            uint32_t pa[4], pl[4];
            split2(s[2*ks][0],   s[2*ks][1],   pa[0], pl[0]);
            split2(s[2*ks][2],   s[2*ks][3],   pa[1], pl[1]);
            split2(s[2*ks+1][0], s[2*ks+1][1], pa[2], pl[2]);
            split2(s[2*ks+1][2], s[2*ks+1][3], pa[3], pl[3]);
            const uint32_t vrow = (ks << 4) + (lane & 15);
#pragma unroll
            for (int nt = 0; nt < 8; nt++) {
                uint32_t off = SWZOFF(vrow, nt);
                uint32_t vh[2], vl[2];
                ldm2t(vh, Vhi + off);
                ldm2t(vl, Vlo + off);
                mma16816(o[nt], pa, vh);
                mma16816(o[nt], pl, vh);
                mma16816(o[nt], pa, vl);
            }
        }

        __syncthreads();   // all reads of buf[nb&1] done

        // ---- prefetch tile nb+2 into the just-freed buffer ----
        if (nb + 2 < nkv) {
            const int nn = (nb + 2) << 6;
            const uint32_t nbuf = sb + (uint32_t)(nb & 1) * 32768u;
#pragma unroll
            for (int u = 0; u < 2; u++) {
                int unit = tid + (u << 8);
                int r = unit >> 3, g = unit & 7;
                uint32_t off = SWZOFF(r, g);
                size_t go = (size_t)(nn + r) * QKVLD + (g << 3);
                cp_async16(nbuf + off,         Kh + go);
                cp_async16(nbuf + 8192 + off,  Kl + go);
                cp_async16(nbuf + 16384 + off, Vh + go);
                cp_async16(nbuf + 24576 + off, Vl + go);
            }
        }
        cp_commit();   // one group per iteration (possibly empty)
    }

    // ---- epilogue: normalize, split to bf16 hi/lo, store ----
    float inv0 = 1.0f / lrow0;
    float inv1 = 1.0f / lrow1;
    int r0 = m0 + (wid << 4) + (lane >> 2);
#pragma unroll
    for (int nt = 0; nt < 8; nt++) {
        int col = h * DH_ + (nt << 3) + ((lane & 3) << 1);
        uint32_t h0, l0, h1, l1;
        split2(o[nt][0] * inv0, o[nt][1] * inv0, h0, l0);
        split2(o[nt][2] * inv1, o[nt][3] * inv1, h1, l1);
        size_t i0 = ((size_t)b * S_ + r0) * D_ + col;
        size_t i1 = ((size_t)b * S_ + r0 + 8) * D_ + col;
        *(uint32_t*)&att_hi[i0] = h0;  *(uint32_t*)&att_lo[i0] = l0;
        *(uint32_t*)&att_hi[i1] = h1;  *(uint32_t*)&att_lo[i1] = l1;
    }
}

// ---------------------------------------------------------------------------
extern "C" void kernel_launch(void* const* d_in, const int* in_sizes, int n_in,
                              void* d_out, int out_size)
{
    (void)in_sizes; (void)n_in; (void)out_size;
    const float* x    = (const float*)d_in[0];
    const float* Wqkv = (const float*)d_in[2];
    const float* bqkv = (const float*)d_in[3];
    const float* Wp   = (const float*)d_in[4];
    const float* bp   = (const float*)d_in[5];
    float* out = (float*)d_out;

    __nv_bfloat16 *xh, *xl, *qh, *ql, *ah, *al, *wqh, *wql, *wph, *wpl;
    cudaGetSymbolAddress((void**)&xh,  g_x_hi);
    cudaGetSymbolAddress((void**)&xl,  g_x_lo);
    cudaGetSymbolAddress((void**)&qh,  g_qkv_hi);
    cudaGetSymbolAddress((void**)&ql,  g_qkv_lo);
    cudaGetSymbolAddress((void**)&ah,  g_att_hi);
    cudaGetSymbolAddress((void**)&al,  g_att_lo);
    cudaGetSymbolAddress((void**)&wqh, g_wqkvT_hi);
    cudaGetSymbolAddress((void**)&wql, g_wqkvT_lo);
    cudaGetSymbolAddress((void**)&wph, g_wpT_hi);
    cudaGetSymbolAddress((void**)&wpl, g_wpT_lo);

    cudaFuncSetAttribute(gemm_abf_obf, cudaFuncAttributeMaxDynamicSharedMemorySize, 65536);
    cudaFuncSetAttribute(gemm_abf_o32, cudaFuncAttributeMaxDynamicSharedMemorySize, 65536);
    cudaFuncSetAttribute(flash_attn_mma, cudaFuncAttributeMaxDynamicSharedMemorySize, 65536);

    // Pre-split inputs/weights
    xsplit<<<(M_TOT * D_) / (256 * 4), 256>>>(x, xh, xl);
    wtrans<<<dim3(QKVLD / 32, D_ / 32), dim3(32, 8)>>>(Wqkv, wqh, wql, D_, QKVLD);
    wtrans<<<dim3(D_ / 32, D_ / 32),   dim3(32, 8)>>>(Wp,   wph, wpl, D_, D_);

    const int M = M_TOT;

    // QKV projection (all-bf16 staging) -> pre-split bf16 (Q scaled 0.125)
    gemm_abf_obf<<<dim3(QKVLD / 128, M / 128), 256, 65536>>>(
        xh, xl, wqh, wql, bqkv, qh, ql, M, QKVLD, D_);

    // Causal flash attention (double-buffered cp.async pipeline)
    flash_attn_mma<<<dim3(S_ / 128, H_, B_), 256, 65536>>>(qh, ql, ah, al);

    // Output projection -> fp32 out
    gemm_abf_o32<<<dim3(D_ / 128, M / 128), 256, 65536>>>(
        ah, al, wph, wpl, bp, out, M, D_, D_);
}

// round 15
// speedup vs baseline: 5.4497x; 1.1333x over previous
#include <cuda_runtime.h>
#include <cuda_bf16.h>
#include <cuda_fp16.h>
#include <cstdint>

#define B_   2
#define S_   2048
#define D_   768
#define H_   12
#define DH_  64
#define QKVLD (3 * D_)   // 2304
#define M_TOT (B_ * S_)  // 4096

// ---------------------------------------------------------------------------
// Scratch (allocation-free rule: __device__ globals)
// x/att: fp16 hi/lo pairs (value = hi + lo, residual ~2^-22).
// qkv:   bf16 hi/lo pairs (flash consumes bf16x3).
// weights: single fp16 (W rounding 2^-12 is the accepted error floor).
// ---------------------------------------------------------------------------
__device__ __half g_x_hi[(size_t)M_TOT * D_];
__device__ __half g_x_lo[(size_t)M_TOT * D_];
__device__ __nv_bfloat16 g_qkv_hi[(size_t)M_TOT * QKVLD]; // Q pre-scaled x0.125
__device__ __nv_bfloat16 g_qkv_lo[(size_t)M_TOT * QKVLD];
__device__ __half g_att_hi[(size_t)M_TOT * D_];
__device__ __half g_att_lo[(size_t)M_TOT * D_];
__device__ __half g_wqkvT_h[(size_t)QKVLD * D_];          // fp16(W_qkv^T)
__device__ __half g_wpT_h[(size_t)D_ * D_];               // fp16(W_proj^T)

// ---------------------------------------------------------------------------
// sm_80-level building blocks (compile clean for compute_103)
// ---------------------------------------------------------------------------
__device__ __forceinline__ uint32_t smem_u32(const void* p) {
    uint32_t a;
    asm("{ .reg .u64 t; cvta.to.shared.u64 t, %1; cvt.u32.u64 %0, t; }" : "=r"(a) : "l"(p));
    return a;
}
__device__ __forceinline__ void cp_async16(uint32_t dst, const void* src) {
    asm volatile("cp.async.cg.shared.global [%0], [%1], 16;" :: "r"(dst), "l"(src));
}
__device__ __forceinline__ void cp_commit() { asm volatile("cp.async.commit_group;"); }
__device__ __forceinline__ void cp_wait0()  { asm volatile("cp.async.wait_group 0;"); }
__device__ __forceinline__ void cp_wait1()  { asm volatile("cp.async.wait_group 1;"); }
__device__ __forceinline__ void cp_wait2()  { asm volatile("cp.async.wait_group 2;"); }

__device__ __forceinline__ void ldm4(uint32_t* r, uint32_t addr) {
    asm volatile("ldmatrix.sync.aligned.m8n8.x4.shared.b16 {%0,%1,%2,%3}, [%4];"
        : "=r"(r[0]), "=r"(r[1]), "=r"(r[2]), "=r"(r[3]) : "r"(addr));
}
__device__ __forceinline__ void ldm2(uint32_t* r, uint32_t addr) {
    asm volatile("ldmatrix.sync.aligned.m8n8.x2.shared.b16 {%0,%1}, [%2];"
        : "=r"(r[0]), "=r"(r[1]) : "r"(addr));
}
__device__ __forceinline__ void ldm2t(uint32_t* r, uint32_t addr) {
    asm volatile("ldmatrix.sync.aligned.m8n8.x2.trans.shared.b16 {%0,%1}, [%2];"
        : "=r"(r[0]), "=r"(r[1]) : "r"(addr));
}
// bf16 MMA (flash)
__device__ __forceinline__ void mma16816(float* d, const uint32_t* a, const uint32_t* b) {
    asm volatile(
        "mma.sync.aligned.m16n8k16.row.col.f32.bf16.bf16.f32 "
        "{%0,%1,%2,%3}, {%4,%5,%6,%7}, {%8,%9}, {%0,%1,%2,%3};"
        : "+f"(d[0]), "+f"(d[1]), "+f"(d[2]), "+f"(d[3])
        : "r"(a[0]), "r"(a[1]), "r"(a[2]), "r"(a[3]), "r"(b[0]), "r"(b[1]));
}
// fp16 MMA (projection GEMMs)
__device__ __forceinline__ void mma16816h(float* d, const uint32_t* a, const uint32_t* b) {
    asm volatile(
        "mma.sync.aligned.m16n8k16.row.col.f32.f16.f16.f32 "
        "{%0,%1,%2,%3}, {%4,%5,%6,%7}, {%8,%9}, {%0,%1,%2,%3};"
        : "+f"(d[0]), "+f"(d[1]), "+f"(d[2]), "+f"(d[3])
        : "r"(a[0]), "r"(a[1]), "r"(a[2]), "r"(a[3]), "r"(b[0]), "r"(b[1]));
}
__device__ __forceinline__ uint32_t pack_bf2(float a, float b) {
    __nv_bfloat162 t = __floats2bfloat162_rn(a, b);
    return *reinterpret_cast<uint32_t*>(&t);
}
__device__ __forceinline__ void split2(float x, float y, uint32_t& hi, uint32_t& lo) {
    __nv_bfloat16 hx = __float2bfloat16(x);
    __nv_bfloat16 hy = __float2bfloat16(y);
    hi = pack_bf2(x, y);
    lo = pack_bf2(x - __bfloat162float(hx), y - __bfloat162float(hy));
}
__device__ __forceinline__ void split2h(float x, float y, uint32_t& hi, uint32_t& lo) {
    __half hx = __float2half_rn(x);
    __half hy = __float2half_rn(y);
    __half2 hp = __halves2half2(hx, hy);
    __half2 lp = __floats2half2_rn(x - __half2float(hx), y - __half2float(hy));
    hi = *reinterpret_cast<uint32_t*>(&hp);
    lo = *reinterpret_cast<uint32_t*>(&lp);
}

// 128B-row swizzle (flash, BK=64 tiles)
#define SWZOFF(r, g) (((uint32_t)(r) << 7) + (((uint32_t)((g) ^ ((r) & 7))) << 4))
// 64B-row swizzle (gemm, BK=32 tiles): conflict-free for stores + ldmatrix
#define SWZ32(r, c)  (((uint32_t)(r) << 6) + (((uint32_t)((c) ^ (((r) >> 1) & 3))) << 4))

// ---------------------------------------------------------------------------
// x split: fp32 -> fp16 hi/lo (elementwise)
// ---------------------------------------------------------------------------
__global__ __launch_bounds__(256) void xsplit_h(
    const float* __restrict__ X,
    __half* __restrict__ Xhi, __half* __restrict__ Xlo)
{
    size_t i = ((size_t)blockIdx.x * 256 + threadIdx.x) << 2;
    float4 v = *(const float4*)(X + i);
    uint32_t h0, l0, h1, l1;
    split2h(v.x, v.y, h0, l0);
    split2h(v.z, v.w, h1, l1);
    *(uint2*)&Xhi[i] = make_uint2(h0, h1);
    *(uint2*)&Xlo[i] = make_uint2(l0, l1);
}

// ---------------------------------------------------------------------------
// Weight transpose + fp16 round: W[K,N] -> T[N,K] (single fp16)
// ---------------------------------------------------------------------------
__global__ void wtrans_h(const float* __restrict__ W,
                         __half* __restrict__ Th, int K, int N)
{
    __shared__ float t[32][33];
    int bx = blockIdx.x << 5;
    int by = blockIdx.y << 5;
    int tx = threadIdx.x, ty = threadIdx.y;
#pragma unroll
    for (int j = 0; j < 4; j++)
        t[ty + j * 8][tx] = W[(size_t)(by + ty + j * 8) * N + bx + tx];
    __syncthreads();
#pragma unroll
    for (int j = 0; j < 4; j++)
        Th[(size_t)(bx + ty + j * 8) * K + by + tx] = __float2half_rn(t[tx][ty + j * 8]);
}

// ---------------------------------------------------------------------------
// fp16x2 tensor-core GEMM, 3-stage cp.async pipeline, BK=32.
// C = (Ahi+Alo) @ fp16(W)^T  ( == A @ fp16(W)^T exactly, residual 2^-22 )
// Stage = 24KB {Ahi 8K, Alo 8K, B 8K}; 3 stages = 72KB; 2 CTAs/SM.
// mode 0: C32 = acc + bias (fp32 out)
// mode 1: split(acc + bias, xQscale) -> bf16 hi/lo (QKV output)
// ---------------------------------------------------------------------------
__global__ __launch_bounds__(256, 2) void gemm_h2(
    const __half* __restrict__ Athi,
    const __half* __restrict__ Atlo,
    const __half* __restrict__ Bt,
    const float* __restrict__ bias,
    float* __restrict__ C32,
    __nv_bfloat16* __restrict__ Ohi, __nv_bfloat16* __restrict__ Olo,
    int M, int Ntot, int K, int mode)
{
    extern __shared__ __align__(1024) uint8_t smem[];
    const uint32_t sb = smem_u32(smem);

    const int tid  = threadIdx.x;
    const int lane = tid & 31;
    const int wid  = tid >> 5;
    const int wm   = wid & 1;
    const int wn   = wid >> 1;
    const int m0   = blockIdx.y << 7;
    const int n0   = blockIdx.x << 7;

    float acc[4][4][4];
#pragma unroll
    for (int mt = 0; mt < 4; mt++)
#pragma unroll
        for (int nt = 0; nt < 4; nt++)
#pragma unroll
            for (int e = 0; e < 4; e++) acc[mt][nt][e] = 0.f;

    const int aRow = lane & 15;
    const int aKs  = lane >> 4;
    const int bRow = lane & 7;
    const int bKs  = (lane >> 3) & 1;
    const int nstages = K >> 5;   // 24

    // stage issue: 3 regions x 512 16B-units, 2 units/thread/region
#define G_ISSUE(s) do {                                                        \
        const uint32_t buf = sb + (uint32_t)((s) % 3) * 24576u;                \
        const int k0 = (s) << 5;                                               \
        _Pragma("unroll")                                                      \
        for (int u = 0; u < 2; u++) {                                          \
            int unit = tid + (u << 8);                                         \
            int r = unit >> 2, c = unit & 3;                                   \
            uint32_t off = SWZ32(r, c);                                        \
            int gcol = k0 + (c << 3);                                          \
            cp_async16(buf + off,         Athi + (size_t)(m0 + r) * K + gcol); \
            cp_async16(buf + 8192 + off,  Atlo + (size_t)(m0 + r) * K + gcol); \
            cp_async16(buf + 16384 + off, Bt   + (size_t)(n0 + r) * K + gcol); \
        }                                                                      \
    } while (0)

    G_ISSUE(0); cp_commit();
    G_ISSUE(1); cp_commit();
    G_ISSUE(2); cp_commit();

    for (int s = 0; s < nstages; s++) {
        const uint32_t buf = sb + (uint32_t)(s % 3) * 24576u;
        cp_wait2();
        __syncthreads();

#pragma unroll
        for (int ks = 0; ks < 2; ks++) {
            const int kc = ks << 1;
            uint32_t ah[4][4], al[4][4];
#pragma unroll
            for (int mt = 0; mt < 4; mt++) {
                int row = (wm << 6) + (mt << 4) + aRow;
                uint32_t off = SWZ32(row, kc + aKs);
                ldm4(ah[mt], buf + off);
                ldm4(al[mt], buf + 8192 + off);
            }
            uint32_t bh[4][2];
#pragma unroll
            for (int nt = 0; nt < 4; nt++) {
                int row = (wn << 5) + (nt << 3) + bRow;
                ldm2(bh[nt], buf + 16384 + SWZ32(row, kc + bKs));
            }
#pragma unroll
            for (int mt = 0; mt < 4; mt++)
#pragma unroll
                for (int nt = 0; nt < 4; nt++) {
                    mma16816h(acc[mt][nt], ah[mt], bh[nt]);
                    mma16816h(acc[mt][nt], al[mt], bh[nt]);
                }
        }

        __syncthreads();
        if (s + 3 < nstages) G_ISSUE(s + 3);
        cp_commit();
    }
#undef G_ISSUE

    // ---- epilogue ----
#pragma unroll
    for (int mt = 0; mt < 4; mt++) {
        int row = m0 + (wm << 6) + (mt << 4) + (lane >> 2);
#pragma unroll
        for (int nt = 0; nt < 4; nt++) {
            int col = n0 + (wn << 5) + (nt << 3) + ((lane & 3) << 1);
            float2 bv = *(const float2*)&bias[col];
            if (mode == 0) {
                float2 o0, o1;
                o0.x = acc[mt][nt][0] + bv.x;
                o0.y = acc[mt][nt][1] + bv.y;
                o1.x = acc[mt][nt][2] + bv.x;
                o1.y = acc[mt][nt][3] + bv.y;
                *(float2*)&C32[(size_t)row * Ntot + col]       = o0;
                *(float2*)&C32[(size_t)(row + 8) * Ntot + col] = o1;
            } else {
                float sc = (col < D_) ? 0.125f : 1.0f;   // scale Q part (exact)
                float x0 = (acc[mt][nt][0] + bv.x) * sc;
                float y0 = (acc[mt][nt][1] + bv.y) * sc;
                float x1 = (acc[mt][nt][2] + bv.x) * sc;
                float y1 = (acc[mt][nt][3] + bv.y) * sc;
                uint32_t h0, l0, h1, l1;
                split2(x0, y0, h0, l0);
                split2(x1, y1, h1, l1);
                size_t i0 = (size_t)row * Ntot + col;
                size_t i1 = (size_t)(row + 8) * Ntot + col;
                *(uint32_t*)&Ohi[i0] = h0;  *(uint32_t*)&Olo[i0] = l0;
                *(uint32_t*)&Ohi[i1] = h1;  *(uint32_t*)&Olo[i1] = l1;
            }
        }
    }
}

// ---------------------------------------------------------------------------
// Flash attention (mma.sync bf16x3), causal, double-buffered K/V pipeline.
// Unchanged from R13 (passing) except att output is fp16 hi/lo.
// ---------------------------------------------------------------------------
__global__ __launch_bounds__(256, 2) void flash_attn_mma(
    const __nv_bfloat16* __restrict__ qkv_hi,
    const __nv_bfloat16* __restrict__ qkv_lo,
    __half* __restrict__ att_hi,
    __half* __restrict__ att_lo)
{
    extern __shared__ __align__(1024) uint8_t sm[];
    const uint32_t sb = smem_u32(sm);

    const int tid  = threadIdx.x;
    const int lane = tid & 31;
    const int wid  = tid >> 5;
    const int mblk = (int)gridDim.x - 1 - (int)blockIdx.x;  // heavy first
    const int h    = blockIdx.y;
    const int b    = blockIdx.z;
    const int m0   = mblk << 7;

    const size_t rowbase = (size_t)b * S_ * QKVLD + h * DH_;
    const __nv_bfloat16* Qh = qkv_hi + rowbase;
    const __nv_bfloat16* Ql = qkv_lo + rowbase;
    const __nv_bfloat16* Kh = Qh + D_;
    const __nv_bfloat16* Kl = Ql + D_;
    const __nv_bfloat16* Vh = Qh + 2 * D_;
    const __nv_bfloat16* Vl = Ql + 2 * D_;

    // ---- stage Q via cp.async (group 0) ----
#pragma unroll
    for (int u = 0; u < 4; u++) {
        int unit = tid + (u << 8);
        int r = unit >> 3, g = unit & 7;
        uint32_t off = SWZOFF(r, g);
        cp_async16(sb + off,         Qh + (size_t)(m0 + r) * QKVLD + (g << 3));
        cp_async16(sb + 16384 + off, Ql + (size_t)(m0 + r) * QKVLD + (g << 3));
    }
    cp_commit();
    cp_wait0();
    __syncthreads();

    // ---- Q fragments (register-resident) ----
    uint32_t qh[4][4], ql[4][4];
    const int aRow = lane & 15;
    const int aKs  = lane >> 4;
#pragma unroll
    for (int ks = 0; ks < 4; ks++) {
        uint32_t off = SWZOFF((wid << 4) + aRow, (ks << 1) + aKs);
        ldm4(qh[ks], sb + off);
        ldm4(ql[ks], sb + 16384 + off);
    }
    __syncthreads();   // Q reads done before tile 0 overwrites buffer 0

    const int rbase = m0 + (wid << 4) + (lane >> 2);
    const int nkv = 2 * mblk + 2;

    // ---- prologue issues: tile 0 (group 1), tile 1 (group 2) ----
    {
        const int n0 = 0;
#pragma unroll
        for (int u = 0; u < 2; u++) {
            int unit = tid + (u << 8);
            int r = unit >> 3, g = unit & 7;
            uint32_t off = SWZOFF(r, g);
            size_t go = (size_t)(n0 + r) * QKVLD + (g << 3);
            cp_async16(sb + off,         Kh + go);
            cp_async16(sb + 8192 + off,  Kl + go);
            cp_async16(sb + 16384 + off, Vh + go);
            cp_async16(sb + 24576 + off, Vl + go);
        }
        cp_commit();
        if (nkv > 1) {
            const int n1 = 64;
#pragma unroll
            for (int u = 0; u < 2; u++) {
                int unit = tid + (u << 8);
                int r = unit >> 3, g = unit & 7;
                uint32_t off = SWZOFF(r, g);
                size_t go = (size_t)(n1 + r) * QKVLD + (g << 3);
                cp_async16(sb + 32768 + off, Kh + go);
                cp_async16(sb + 40960 + off, Kl + go);
                cp_async16(sb + 49152 + off, Vh + go);
                cp_async16(sb + 57344 + off, Vl + go);
            }
        }
        cp_commit();
    }

    float o[8][4];
#pragma unroll
    for (int nt = 0; nt < 8; nt++)
#pragma unroll
        for (int e = 0; e < 4; e++) o[nt][e] = 0.f;
    float mrow0 = -1e30f, mrow1 = -1e30f, lrow0 = 0.f, lrow1 = 0.f;

    for (int nb = 0; nb < nkv; nb++) {
        const int n0 = nb << 6;
        const uint32_t bufb = sb + (uint32_t)(nb & 1) * 32768u;
        const uint32_t Khi = bufb, Klo = bufb + 8192;
        const uint32_t Vhi = bufb + 16384, Vlo = bufb + 24576;

        cp_wait1();
        __syncthreads();

        // ---- S = QK^T (bf16x3) ----
        float s[8][4];
#pragma unroll
        for (int nt = 0; nt < 8; nt++)
#pragma unroll
            for (int e = 0; e < 4; e++) s[nt][e] = 0.f;

#pragma unroll
        for (int ks = 0; ks < 4; ks++) {
            const uint32_t kc = (ks << 1) + ((lane >> 3) & 1);
#pragma unroll
            for (int nt = 0; nt < 8; nt++) {
                uint32_t off = SWZOFF((nt << 3) + (lane & 7), kc);
                uint32_t bh[2], bl[2];
                ldm2(bh, Khi + off);
                ldm2(bl, Klo + off);
                mma16816(s[nt], qh[ks], bh);
                mma16816(s[nt], ql[ks], bh);
                mma16816(s[nt], qh[ks], bl);
            }
        }

        // ---- causal mask ----
        if (n0 + 63 > m0 + (wid << 4)) {
#pragma unroll
            for (int nt = 0; nt < 8; nt++) {
                int col = n0 + (nt << 3) + ((lane & 3) << 1);
                if (col     > rbase)     s[nt][0] = -1e30f;
                if (col + 1 > rbase)     s[nt][1] = -1e30f;
                if (col     > rbase + 8) s[nt][2] = -1e30f;
                if (col + 1 > rbase + 8) s[nt][3] = -1e30f;
            }
        }

        // ---- online softmax ----
        float mx0 = s[0][0], mx1 = s[0][2];
#pragma unroll
        for (int nt = 0; nt < 8; nt++) {
            mx0 = fmaxf(mx0, fmaxf(s[nt][0], s[nt][1]));
            mx1 = fmaxf(mx1, fmaxf(s[nt][2], s[nt][3]));
        }
        mx0 = fmaxf(mx0, __shfl_xor_sync(0xffffffffu, mx0, 1));
        mx0 = fmaxf(mx0, __shfl_xor_sync(0xffffffffu, mx0, 2));
        mx1 = fmaxf(mx1, __shfl_xor_sync(0xffffffffu, mx1, 1));
        mx1 = fmaxf(mx1, __shfl_xor_sync(0xffffffffu, mx1, 2));

        float mn0 = fmaxf(mrow0, mx0);
        float mn1 = fmaxf(mrow1, mx1);
        float al0 = __expf(mrow0 - mn0);
        float al1 = __expf(mrow1 - mn1);
        mrow0 = mn0; mrow1 = mn1;

        float rs0 = 0.f, rs1 = 0.f;
#pragma unroll
        for (int nt = 0; nt < 8; nt++) {
            s[nt][0] = __expf(s[nt][0] - mn0);
            s[nt][1] = __expf(s[nt][1] - mn0);
            s[nt][2] = __expf(s[nt][2] - mn1);
            s[nt][3] = __expf(s[nt][3] - mn1);
            rs0 += s[nt][0] + s[nt][1];
            rs1 += s[nt][2] + s[nt][3];
        }
        rs0 += __shfl_xor_sync(0xffffffffu, rs0, 1);
        rs0 += __shfl_xor_sync(0xffffffffu, rs0, 2);
        rs1 += __shfl_xor_sync(0xffffffffu, rs1, 1);
        rs1 += __shfl_xor_sync(0xffffffffu, rs1, 2);
        lrow0 = lrow0 * al0 + rs0;
        lrow1 = lrow1 * al1 + rs1;

#pragma unroll
        for (int nt = 0; nt < 8; nt++) {
            o[nt][0] *= al0; o[nt][1] *= al0;
            o[nt][2] *= al1; o[nt][3] *= al1;
        }

        // ---- O += P @ V (bf16x3) ----
#pragma unroll
        for (int ks = 0; ks < 4; ks++) {
            uint32_t pa[4], pl[4];
            split2(s[2*ks][0],   s[2*ks][1],   pa[0], pl[0]);
            split2(s[2*ks][2],   s[2*ks][3],   pa[1], pl[1]);
            split2(s[2*ks+1][0], s[2*ks+1][1], pa[2], pl[2]);
            split2(s[2*ks+1][2], s[2*ks+1][3], pa[3], pl[3]);
            const uint32_t vrow = (ks << 4) + (lane & 15);
#pragma unroll
            for (int nt = 0; nt < 8; nt++) {
                uint32_t off = SWZOFF(vrow, nt);
                uint32_t vh[2], vl[2];
                ldm2t(vh, Vhi + off);
                ldm2t(vl, Vlo + off);
                mma16816(o[nt], pa, vh);
                mma16816(o[nt], pl, vh);
                mma16816(o[nt], pa, vl);
            }
        }

        __syncthreads();

        // ---- prefetch tile nb+2 into the just-freed buffer ----
        if (nb + 2 < nkv) {
            const int nn = (nb + 2) << 6;
            const uint32_t nbuf = sb + (uint32_t)(nb & 1) * 32768u;
#pragma unroll
            for (int u = 0; u < 2; u++) {
                int unit = tid + (u << 8);
                int r = unit >> 3, g = unit & 7;
                uint32_t off = SWZOFF(r, g);
                size_t go = (size_t)(nn + r) * QKVLD + (g << 3);
                cp_async16(nbuf + off,         Kh + go);
                cp_async16(nbuf + 8192 + off,  Kl + go);
                cp_async16(nbuf + 16384 + off, Vh + go);
                cp_async16(nbuf + 24576 + off, Vl + go);
            }
        }
        cp_commit();
    }

    // ---- epilogue: normalize, split to fp16 hi/lo, store ----
    float inv0 = 1.0f / lrow0;
    float inv1 = 1.0f / lrow1;
    int r0 = m0 + (wid << 4) + (lane >> 2);
#pragma unroll
    for (int nt = 0; nt < 8; nt++) {
        int col = h * DH_ + (nt << 3) + ((lane & 3) << 1);
        uint32_t h0, l0, h1, l1;
        split2h(o[nt][0] * inv0, o[nt][1] * inv0, h0, l0);
        split2h(o[nt][2] * inv1, o[nt][3] * inv1, h1, l1);
        size_t i0 = ((size_t)b * S_ + r0) * D_ + col;
        size_t i1 = ((size_t)b * S_ + r0 + 8) * D_ + col;
        *(uint32_t*)&att_hi[i0] = h0;  *(uint32_t*)&att_lo[i0] = l0;
        *(uint32_t*)&att_hi[i1] = h1;  *(uint32_t*)&att_lo[i1] = l1;
    }
}

// ---------------------------------------------------------------------------
extern "C" void kernel_launch(void* const* d_in, const int* in_sizes, int n_in,
                              void* d_out, int out_size)
{
    (void)in_sizes; (void)n_in; (void)out_size;
    const float* x    = (const float*)d_in[0];
    const float* Wqkv = (const float*)d_in[2];
    const float* bqkv = (const float*)d_in[3];
    const float* Wp   = (const float*)d_in[4];
    const float* bp   = (const float*)d_in[5];
    float* out = (float*)d_out;

    __half *xh, *xl, *ah, *al, *wqh, *wph;
    __nv_bfloat16 *qh, *ql;
    cudaGetSymbolAddress((void**)&xh,  g_x_hi);
    cudaGetSymbolAddress((void**)&xl,  g_x_lo);
    cudaGetSymbolAddress((void**)&qh,  g_qkv_hi);
    cudaGetSymbolAddress((void**)&ql,  g_qkv_lo);
    cudaGetSymbolAddress((void**)&ah,  g_att_hi);
    cudaGetSymbolAddress((void**)&al,  g_att_lo);
    cudaGetSymbolAddress((void**)&wqh, g_wqkvT_h);
    cudaGetSymbolAddress((void**)&wph, g_wpT_h);

    cudaFuncSetAttribute(gemm_h2, cudaFuncAttributeMaxDynamicSharedMemorySize, 73728);
    cudaFuncSetAttribute(flash_attn_mma, cudaFuncAttributeMaxDynamicSharedMemorySize, 65536);

    // Pre-split input / round weights
    xsplit_h<<<(M_TOT * D_) / (256 * 4), 256>>>(x, xh, xl);
    wtrans_h<<<dim3(QKVLD / 32, D_ / 32), dim3(32, 8)>>>(Wqkv, wqh, D_, QKVLD);
    wtrans_h<<<dim3(D_ / 32, D_ / 32),   dim3(32, 8)>>>(Wp,   wph, D_, D_);

    const int M = M_TOT;

    // QKV projection (fp16x2 pipelined) -> bf16 hi/lo (Q scaled 0.125)
    gemm_h2<<<dim3(QKVLD / 128, M / 128), 256, 73728>>>(
        xh, xl, wqh, bqkv, nullptr, qh, ql, M, QKVLD, D_, 1);

    // Causal flash attention (bf16x3, double-buffered)
    flash_attn_mma<<<dim3(S_ / 128, H_, B_), 256, 65536>>>(qh, ql, ah, al);

    // Output projection (fp16x2 pipelined) -> fp32 out
    gemm_h2<<<dim3(D_ / 128, M / 128), 256, 73728>>>(
        ah, al, wph, bp, out, nullptr, nullptr, M, D_, D_, 0);
}

// round 17
// speedup vs baseline: 6.0451x; 1.1092x over previous
#include <cuda_runtime.h>
#include <cuda_bf16.h>
#include <cuda_fp16.h>
#include <cstdint>

#define B_   2
#define S_   2048
#define D_   768
#define H_   12
#define DH_  64
#define QKVLD (3 * D_)   // 2304
#define M_TOT (B_ * S_)  // 4096

// ---------------------------------------------------------------------------
// Scratch (allocation-free rule: __device__ globals)
// x/att: fp16 hi/lo pairs. qkv: Q,K bf16 hi/lo; V region = single fp16
// (bits stored in g_qkv_hi). weights: single fp16.
// ---------------------------------------------------------------------------
__device__ __half g_x_hi[(size_t)M_TOT * D_];
__device__ __half g_x_lo[(size_t)M_TOT * D_];
__device__ __nv_bfloat16 g_qkv_hi[(size_t)M_TOT * QKVLD]; // Q x0.125; V=fp16 bits
__device__ __nv_bfloat16 g_qkv_lo[(size_t)M_TOT * QKVLD];
__device__ __half g_att_hi[(size_t)M_TOT * D_];
__device__ __half g_att_lo[(size_t)M_TOT * D_];
__device__ __half g_wqkvT_h[(size_t)QKVLD * D_];          // fp16(W_qkv^T)
__device__ __half g_wpT_h[(size_t)D_ * D_];               // fp16(W_proj^T)

// ---------------------------------------------------------------------------
// sm_80-level building blocks (compile clean for compute_103)
// ---------------------------------------------------------------------------
__device__ __forceinline__ uint32_t smem_u32(const void* p) {
    uint32_t a;
    asm("{ .reg .u64 t; cvta.to.shared.u64 t, %1; cvt.u32.u64 %0, t; }" : "=r"(a) : "l"(p));
    return a;
}
__device__ __forceinline__ void cp_async16(uint32_t dst, const void* src) {
    asm volatile("cp.async.cg.shared.global [%0], [%1], 16;" :: "r"(dst), "l"(src));
}
__device__ __forceinline__ void cp_commit() { asm volatile("cp.async.commit_group;"); }
__device__ __forceinline__ void cp_wait0()  { asm volatile("cp.async.wait_group 0;"); }
__device__ __forceinline__ void cp_wait1()  { asm volatile("cp.async.wait_group 1;"); }
__device__ __forceinline__ void cp_wait2()  { asm volatile("cp.async.wait_group 2;"); }

__device__ __forceinline__ void ldm4(uint32_t* r, uint32_t addr) {
    asm volatile("ldmatrix.sync.aligned.m8n8.x4.shared.b16 {%0,%1,%2,%3}, [%4];"
        : "=r"(r[0]), "=r"(r[1]), "=r"(r[2]), "=r"(r[3]) : "r"(addr));
}
__device__ __forceinline__ void ldm2(uint32_t* r, uint32_t addr) {
    asm volatile("ldmatrix.sync.aligned.m8n8.x2.shared.b16 {%0,%1}, [%2];"
        : "=r"(r[0]), "=r"(r[1]) : "r"(addr));
}
__device__ __forceinline__ void ldm2t(uint32_t* r, uint32_t addr) {
    asm volatile("ldmatrix.sync.aligned.m8n8.x2.trans.shared.b16 {%0,%1}, [%2];"
        : "=r"(r[0]), "=r"(r[1]) : "r"(addr));
}
// bf16 MMA (flash QK)
__device__ __forceinline__ void mma16816(float* d, const uint32_t* a, const uint32_t* b) {
    asm volatile(
        "mma.sync.aligned.m16n8k16.row.col.f32.bf16.bf16.f32 "
        "{%0,%1,%2,%3}, {%4,%5,%6,%7}, {%8,%9}, {%0,%1,%2,%3};"
        : "+f"(d[0]), "+f"(d[1]), "+f"(d[2]), "+f"(d[3])
        : "r"(a[0]), "r"(a[1]), "r"(a[2]), "r"(a[3]), "r"(b[0]), "r"(b[1]));
}
// fp16 MMA (GEMMs + flash PV)
__device__ __forceinline__ void mma16816h(float* d, const uint32_t* a, const uint32_t* b) {
    asm volatile(
        "mma.sync.aligned.m16n8k16.row.col.f32.f16.f16.f32 "
        "{%0,%1,%2,%3}, {%4,%5,%6,%7}, {%8,%9}, {%0,%1,%2,%3};"
        : "+f"(d[0]), "+f"(d[1]), "+f"(d[2]), "+f"(d[3])
        : "r"(a[0]), "r"(a[1]), "r"(a[2]), "r"(a[3]), "r"(b[0]), "r"(b[1]));
}
__device__ __forceinline__ uint32_t pack_bf2(float a, float b) {
    __nv_bfloat162 t = __floats2bfloat162_rn(a, b);
    return *reinterpret_cast<uint32_t*>(&t);
}
__device__ __forceinline__ void split2(float x, float y, uint32_t& hi, uint32_t& lo) {
    __nv_bfloat16 hx = __float2bfloat16(x);
    __nv_bfloat16 hy = __float2bfloat16(y);
    hi = pack_bf2(x, y);
    lo = pack_bf2(x - __bfloat162float(hx), y - __bfloat162float(hy));
}
__device__ __forceinline__ void split2h(float x, float y, uint32_t& hi, uint32_t& lo) {
    __half hx = __float2half_rn(x);
    __half hy = __float2half_rn(y);
    __half2 hp = __halves2half2(hx, hy);
    __half2 lp = __floats2half2_rn(x - __half2float(hx), y - __half2float(hy));
    hi = *reinterpret_cast<uint32_t*>(&hp);
    lo = *reinterpret_cast<uint32_t*>(&lp);
}
__device__ __forceinline__ uint32_t pack_h2(float x, float y) {
    __half2 hp = __floats2half2_rn(x, y);
    return *reinterpret_cast<uint32_t*>(&hp);
}

// 128B-row swizzle (flash, 64-row x 128B tiles)
#define SWZOFF(r, g) (((uint32_t)(r) << 7) + (((uint32_t)((g) ^ ((r) & 7))) << 4))
// 64B-row swizzle (gemm, BK=32 tiles)
#define SWZ32(r, c)  (((uint32_t)(r) << 6) + (((uint32_t)((c) ^ (((r) >> 1) & 3))) << 4))

// ---------------------------------------------------------------------------
// x split: fp32 -> fp16 hi/lo (elementwise)
// ---------------------------------------------------------------------------
__global__ __launch_bounds__(256) void xsplit_h(
    const float* __restrict__ X,
    __half* __restrict__ Xhi, __half* __restrict__ Xlo)
{
    size_t i = ((size_t)blockIdx.x * 256 + threadIdx.x) << 2;
    float4 v = *(const float4*)(X + i);
    uint32_t h0, l0, h1, l1;
    split2h(v.x, v.y, h0, l0);
    split2h(v.z, v.w, h1, l1);
    *(uint2*)&Xhi[i] = make_uint2(h0, h1);
    *(uint2*)&Xlo[i] = make_uint2(l0, l1);
}

// ---------------------------------------------------------------------------
// Weight transpose + fp16 round: W[K,N] -> T[N,K] (single fp16)
// ---------------------------------------------------------------------------
__global__ void wtrans_h(const float* __restrict__ W,
                         __half* __restrict__ Th, int K, int N)
{
    __shared__ float t[32][33];
    int bx = blockIdx.x << 5;
    int by = blockIdx.y << 5;
    int tx = threadIdx.x, ty = threadIdx.y;
#pragma unroll
    for (int j = 0; j < 4; j++)
        t[ty + j * 8][tx] = W[(size_t)(by + ty + j * 8) * N + bx + tx];
    __syncthreads();
#pragma unroll
    for (int j = 0; j < 4; j++)
        Th[(size_t)(bx + ty + j * 8) * K + by + tx] = __float2half_rn(t[tx][ty + j * 8]);
}

// ---------------------------------------------------------------------------
// fp16x2 tensor-core GEMM, 3-stage cp.async pipeline, BK=32.
// C = (Ahi+Alo) @ fp16(W)^T
// mode 0: C32 = acc + bias (fp32 out)
// mode 1: QKV output: Q cols (<D) x0.125 -> bf16 hi/lo; K cols -> bf16 hi/lo;
//         V cols (>=2D) -> single fp16 (bits into Ohi only).
// ---------------------------------------------------------------------------
__global__ __launch_bounds__(256, 2) void gemm_h2(
    const __half* __restrict__ Athi,
    const __half* __restrict__ Atlo,
    const __half* __restrict__ Bt,
    const float* __restrict__ bias,
    float* __restrict__ C32,
    __nv_bfloat16* __restrict__ Ohi, __nv_bfloat16* __restrict__ Olo,
    int M, int Ntot, int K, int mode)
{
    extern __shared__ __align__(1024) uint8_t smem[];
    const uint32_t sb = smem_u32(smem);

    const int tid  = threadIdx.x;
    const int lane = tid & 31;
    const int wid  = tid >> 5;
    const int wm   = wid & 1;
    const int wn   = wid >> 1;
    const int m0   = blockIdx.y << 7;
    const int n0   = blockIdx.x << 7;

    float acc[4][4][4];
#pragma unroll
    for (int mt = 0; mt < 4; mt++)
#pragma unroll
        for (int nt = 0; nt < 4; nt++)
#pragma unroll
            for (int e = 0; e < 4; e++) acc[mt][nt][e] = 0.f;

    const int aRow = lane & 15;
    const int aKs  = lane >> 4;
    const int bRow = lane & 7;
    const int bKs  = (lane >> 3) & 1;
    const int nstages = K >> 5;   // 24

#define G_ISSUE(s) do {                                                        \
        const uint32_t buf = sb + (uint32_t)((s) % 3) * 24576u;                \
        const int k0 = (s) << 5;                                               \
        _Pragma("unroll")                                                      \
        for (int u = 0; u < 2; u++) {                                          \
            int unit = tid + (u << 8);                                         \
            int r = unit >> 2, c = unit & 3;                                   \
            uint32_t off = SWZ32(r, c);                                        \
            int gcol = k0 + (c << 3);                                          \
            cp_async16(buf + off,         Athi + (size_t)(m0 + r) * K + gcol); \
            cp_async16(buf + 8192 + off,  Atlo + (size_t)(m0 + r) * K + gcol); \
            cp_async16(buf + 16384 + off, Bt   + (size_t)(n0 + r) * K + gcol); \
        }                                                                      \
    } while (0)

    G_ISSUE(0); cp_commit();
    G_ISSUE(1); cp_commit();
    G_ISSUE(2); cp_commit();

    for (int s = 0; s < nstages; s++) {
        const uint32_t buf = sb + (uint32_t)(s % 3) * 24576u;
        cp_wait2();
        __syncthreads();

#pragma unroll
        for (int ks = 0; ks < 2; ks++) {
            const int kc = ks << 1;
            uint32_t ah[4][4], al[4][4];
#pragma unroll
            for (int mt = 0; mt < 4; mt++) {
                int row = (wm << 6) + (mt << 4) + aRow;
                uint32_t off = SWZ32(row, kc + aKs);
                ldm4(ah[mt], buf + off);
                ldm4(al[mt], buf + 8192 + off);
            }
            uint32_t bh[4][2];
#pragma unroll
            for (int nt = 0; nt < 4; nt++) {
                int row = (wn << 5) + (nt << 3) + bRow;
                ldm2(bh[nt], buf + 16384 + SWZ32(row, kc + bKs));
            }
#pragma unroll
            for (int mt = 0; mt < 4; mt++)
#pragma unroll
                for (int nt = 0; nt < 4; nt++) {
                    mma16816h(acc[mt][nt], ah[mt], bh[nt]);
                    mma16816h(acc[mt][nt], al[mt], bh[nt]);
                }
        }

        __syncthreads();
        if (s + 3 < nstages) G_ISSUE(s + 3);
        cp_commit();
    }
#undef G_ISSUE

    // ---- epilogue ----
#pragma unroll
    for (int mt = 0; mt < 4; mt++) {
        int row = m0 + (wm << 6) + (mt << 4) + (lane >> 2);
#pragma unroll
        for (int nt = 0; nt < 4; nt++) {
            int col = n0 + (wn << 5) + (nt << 3) + ((lane & 3) << 1);
            float2 bv = *(const float2*)&bias[col];
            if (mode == 0) {
                float2 o0, o1;
                o0.x = acc[mt][nt][0] + bv.x;
                o0.y = acc[mt][nt][1] + bv.y;
                o1.x = acc[mt][nt][2] + bv.x;
                o1.y = acc[mt][nt][3] + bv.y;
                *(float2*)&C32[(size_t)row * Ntot + col]       = o0;
                *(float2*)&C32[(size_t)(row + 8) * Ntot + col] = o1;
            } else if (col >= 2 * D_) {
                // V region: single fp16 (bits into Ohi)
                size_t i0 = (size_t)row * Ntot + col;
                size_t i1 = (size_t)(row + 8) * Ntot + col;
                *(uint32_t*)&Ohi[i0] = pack_h2(acc[mt][nt][0] + bv.x,
                                               acc[mt][nt][1] + bv.y);
                *(uint32_t*)&Ohi[i1] = pack_h2(acc[mt][nt][2] + bv.x,
                                               acc[mt][nt][3] + bv.y);
            } else {
                float sc = (col < D_) ? 0.125f : 1.0f;   // scale Q part (exact)
                float x0 = (acc[mt][nt][0] + bv.x) * sc;
                float y0 = (acc[mt][nt][1] + bv.y) * sc;
                float x1 = (acc[mt][nt][2] + bv.x) * sc;
                float y1 = (acc[mt][nt][3] + bv.y) * sc;
                uint32_t h0, l0, h1, l1;
                split2(x0, y0, h0, l0);
                split2(x1, y1, h1, l1);
                size_t i0 = (size_t)row * Ntot + col;
                size_t i1 = (size_t)(row + 8) * Ntot + col;
                *(uint32_t*)&Ohi[i0] = h0;  *(uint32_t*)&Olo[i0] = l0;
                *(uint32_t*)&Ohi[i1] = h1;  *(uint32_t*)&Olo[i1] = l1;
            }
        }
    }
}

// ---------------------------------------------------------------------------
// Flash attention, causal, double-buffered. QK = bf16x3; PV = fp16x2
// (P fp16 hi/lo in registers, V single fp16). Stage = 24KB {Khi,Klo,Vh};
// 2 stages = 48KB; 2 CTAs/SM.
// ---------------------------------------------------------------------------
__global__ __launch_bounds__(256, 2) void flash_attn_mma(
    const __nv_bfloat16* __restrict__ qkv_hi,
    const __nv_bfloat16* __restrict__ qkv_lo,
    __half* __restrict__ att_hi,
    __half* __restrict__ att_lo)
{
    extern __shared__ __align__(1024) uint8_t sm[];
    const uint32_t sb = smem_u32(sm);

    const int tid  = threadIdx.x;
    const int lane = tid & 31;
    const int wid  = tid >> 5;
    const int mblk = (int)gridDim.x - 1 - (int)blockIdx.x;  // heavy first
    const int h    = blockIdx.y;
    const int b    = blockIdx.z;
    const int m0   = mblk << 7;

    const size_t rowbase = (size_t)b * S_ * QKVLD + h * DH_;
    const __nv_bfloat16* Qh = qkv_hi + rowbase;
    const __nv_bfloat16* Ql = qkv_lo + rowbase;
    const __nv_bfloat16* Kh = Qh + D_;
    const __nv_bfloat16* Kl = Ql + D_;
    const __half* Vh = reinterpret_cast<const __half*>(qkv_hi + rowbase + 2 * D_);

    // ---- stage Q via cp.async (group 0): Qhi at sb, Qlo at sb+16K ----
#pragma unroll
    for (int u = 0; u < 4; u++) {
        int unit = tid + (u << 8);
        int r = unit >> 3, g = unit & 7;
        uint32_t off = SWZOFF(r, g);
        cp_async16(sb + off,         Qh + (size_t)(m0 + r) * QKVLD + (g << 3));
        cp_async16(sb + 16384 + off, Ql + (size_t)(m0 + r) * QKVLD + (g << 3));
    }
    cp_commit();
    cp_wait0();
    __syncthreads();

    // ---- Q fragments (register-resident) ----
    uint32_t qh[4][4], ql[4][4];
    const int aRow = lane & 15;
    const int aKs  = lane >> 4;
#pragma unroll
    for (int ks = 0; ks < 4; ks++) {
        uint32_t off = SWZOFF((wid << 4) + aRow, (ks << 1) + aKs);
        ldm4(qh[ks], sb + off);
        ldm4(ql[ks], sb + 16384 + off);
    }
    __syncthreads();   // Q reads done before tile staging overwrites

    const int rbase = m0 + (wid << 4) + (lane >> 2);
    const int nkv = 2 * mblk + 2;

    // stage issue helper: 3 regions x 512 16B-units, 2 units/thread
#define F_ISSUE(nb_) do {                                                      \
        const int nn = (nb_) << 6;                                             \
        const uint32_t buf = sb + (uint32_t)((nb_) & 1) * 24576u;              \
        _Pragma("unroll")                                                      \
        for (int u = 0; u < 2; u++) {                                          \
            int unit = tid + (u << 8);                                         \
            int r = unit >> 3, g = unit & 7;                                   \
            uint32_t off = SWZOFF(r, g);                                       \
            size_t go = (size_t)(nn + r) * QKVLD + (g << 3);                   \
            cp_async16(buf + off,         Kh + go);                            \
            cp_async16(buf + 8192 + off,  Kl + go);                            \
            cp_async16(buf + 16384 + off, Vh + go);                            \
        }                                                                      \
    } while (0)

    // ---- prologue: tile 0 (group 1), tile 1 (group 2) ----
    F_ISSUE(0);
    cp_commit();
    if (nkv > 1) F_ISSUE(1);
    cp_commit();

    float o[8][4];
#pragma unroll
    for (int nt = 0; nt < 8; nt++)
#pragma unroll
        for (int e = 0; e < 4; e++) o[nt][e] = 0.f;
    float mrow0 = -1e30f, mrow1 = -1e30f, lrow0 = 0.f, lrow1 = 0.f;

    for (int nb = 0; nb < nkv; nb++) {
        const int n0 = nb << 6;
        const uint32_t bufb = sb + (uint32_t)(nb & 1) * 24576u;
        const uint32_t Khi_s = bufb, Klo_s = bufb + 8192, Vh_s = bufb + 16384;

        cp_wait1();
        __syncthreads();

        // ---- S = QK^T (bf16x3) ----
        float s[8][4];
#pragma unroll
        for (int nt = 0; nt < 8; nt++)
#pragma unroll
            for (int e = 0; e < 4; e++) s[nt][e] = 0.f;

#pragma unroll
        for (int ks = 0; ks < 4; ks++) {
            const uint32_t kc = (ks << 1) + ((lane >> 3) & 1);
#pragma unroll
            for (int nt = 0; nt < 8; nt++) {
                uint32_t off = SWZOFF((nt << 3) + (lane & 7), kc);
                uint32_t bh[2], bl[2];
                ldm2(bh, Khi_s + off);
                ldm2(bl, Klo_s + off);
                mma16816(s[nt], qh[ks], bh);
                mma16816(s[nt], ql[ks], bh);
                mma16816(s[nt], qh[ks], bl);
            }
        }

        // ---- causal mask ----
        if (n0 + 63 > m0 + (wid << 4)) {
#pragma unroll
            for (int nt = 0; nt < 8; nt++) {
                int col = n0 + (nt << 3) + ((lane & 3) << 1);
                if (col     > rbase)     s[nt][0] = -1e30f;
                if (col + 1 > rbase)     s[nt][1] = -1e30f;
                if (col     > rbase + 8) s[nt][2] = -1e30f;
                if (col + 1 > rbase + 8) s[nt][3] = -1e30f;
            }
        }

        // ---- online softmax ----
        float mx0 = s[0][0], mx1 = s[0][2];
#pragma unroll
        for (int nt = 0; nt < 8; nt++) {
            mx0 = fmaxf(mx0, fmaxf(s[nt][0], s[nt][1]));
            mx1 = fmaxf(mx1, fmaxf(s[nt][2], s[nt][3]));
        }
        mx0 = fmaxf(mx0, __shfl_xor_sync(0xffffffffu, mx0, 1));
        mx0 = fmaxf(mx0, __shfl_xor_sync(0xffffffffu, mx0, 2));
        mx1 = fmaxf(mx1, __shfl_xor_sync(0xffffffffu, mx1, 1));
        mx1 = fmaxf(mx1, __shfl_xor_sync(0xffffffffu, mx1, 2));

        float mn0 = fmaxf(mrow0, mx0);
        float mn1 = fmaxf(mrow1, mx1);
        float al0 = __expf(mrow0 - mn0);
        float al1 = __expf(mrow1 - mn1);
        mrow0 = mn0; mrow1 = mn1;

        float rs0 = 0.f, rs1 = 0.f;
#pragma unroll
        for (int nt = 0; nt < 8; nt++) {
            s[nt][0] = __expf(s[nt][0] - mn0);
            s[nt][1] = __expf(s[nt][1] - mn0);
            s[nt][2] = __expf(s[nt][2] - mn1);
            s[nt][3] = __expf(s[nt][3] - mn1);
            rs0 += s[nt][0] + s[nt][1];
            rs1 += s[nt][2] + s[nt][3];
        }
        rs0 += __shfl_xor_sync(0xffffffffu, rs0, 1);
        rs0 += __shfl_xor_sync(0xffffffffu, rs0, 2);
        rs1 += __shfl_xor_sync(0xffffffffu, rs1, 1);
        rs1 += __shfl_xor_sync(0xffffffffu, rs1, 2);
        lrow0 = lrow0 * al0 + rs0;
        lrow1 = lrow1 * al1 + rs1;

#pragma unroll
        for (int nt = 0; nt < 8; nt++) {
            o[nt][0] *= al0; o[nt][1] *= al0;
            o[nt][2] *= al1; o[nt][3] *= al1;
        }

        // ---- O += P @ V (fp16x2: P hi/lo fp16, V single fp16) ----
#pragma unroll
        for (int ks = 0; ks < 4; ks++) {
            uint32_t pa[4], pl[4];
            split2h(s[2*ks][0],   s[2*ks][1],   pa[0], pl[0]);
            split2h(s[2*ks][2],   s[2*ks][3],   pa[1], pl[1]);
            split2h(s[2*ks+1][0], s[2*ks+1][1], pa[2], pl[2]);
            split2h(s[2*ks+1][2], s[2*ks+1][3], pa[3], pl[3]);
            const uint32_t vrow = (ks << 4) + (lane & 15);
#pragma unroll
            for (int nt = 0; nt < 8; nt++) {
                uint32_t vh[2];
                ldm2t(vh, Vh_s + SWZOFF(vrow, nt));
                mma16816h(o[nt], pa, vh);
                mma16816h(o[nt], pl, vh);
            }
        }

        __syncthreads();

        // ---- prefetch tile nb+2 into the just-freed buffer ----
        if (nb + 2 < nkv) F_ISSUE(nb + 2);
        cp_commit();
    }
#undef F_ISSUE

    // ---- epilogue: normalize, split to fp16 hi/lo, store ----
    float inv0 = 1.0f / lrow0;
    float inv1 = 1.0f / lrow1;
    int r0 = m0 + (wid << 4) + (lane >> 2);
#pragma unroll
    for (int nt = 0; nt < 8; nt++) {
        int col = h * DH_ + (nt << 3) + ((lane & 3) << 1);
        uint32_t h0, l0, h1, l1;
        split2h(o[nt][0] * inv0, o[nt][1] * inv0, h0, l0);
        split2h(o[nt][2] * inv1, o[nt][3] * inv1, h1, l1);
        size_t i0 = ((size_t)b * S_ + r0) * D_ + col;
        size_t i1 = ((size_t)b * S_ + r0 + 8) * D_ + col;
        *(uint32_t*)&att_hi[i0] = h0;  *(uint32_t*)&att_lo[i0] = l0;
        *(uint32_t*)&att_hi[i1] = h1;  *(uint32_t*)&att_lo[i1] = l1;
    }
}

// ---------------------------------------------------------------------------
extern "C" void kernel_launch(void* const* d_in, const int* in_sizes, int n_in,
                              void* d_out, int out_size)
{
    (void)in_sizes; (void)n_in; (void)out_size;
    const float* x    = (const float*)d_in[0];
    const float* Wqkv = (const float*)d_in[2];
    const float* bqkv = (const float*)d_in[3];
    const float* Wp   = (const float*)d_in[4];
    const float* bp   = (const float*)d_in[5];
    float* out = (float*)d_out;

    __half *xh, *xl, *ah, *al, *wqh, *wph;
    __nv_bfloat16 *qh, *ql;
    cudaGetSymbolAddress((void**)&xh,  g_x_hi);
    cudaGetSymbolAddress((void**)&xl,  g_x_lo);
    cudaGetSymbolAddress((void**)&qh,  g_qkv_hi);
    cudaGetSymbolAddress((void**)&ql,  g_qkv_lo);
    cudaGetSymbolAddress((void**)&ah,  g_att_hi);
    cudaGetSymbolAddress((void**)&al,  g_att_lo);
    cudaGetSymbolAddress((void**)&wqh, g_wqkvT_h);
    cudaGetSymbolAddress((void**)&wph, g_wpT_h);

    cudaFuncSetAttribute(gemm_h2, cudaFuncAttributeMaxDynamicSharedMemorySize, 73728);
    cudaFuncSetAttribute(flash_attn_mma, cudaFuncAttributeMaxDynamicSharedMemorySize, 49152);

    // Pre-split input / round weights
    xsplit_h<<<(M_TOT * D_) / (256 * 4), 256>>>(x, xh, xl);
    wtrans_h<<<dim3(QKVLD / 32, D_ / 32), dim3(32, 8)>>>(Wqkv, wqh, D_, QKVLD);
    wtrans_h<<<dim3(D_ / 32, D_ / 32),   dim3(32, 8)>>>(Wp,   wph, D_, D_);

    const int M = M_TOT;

    // QKV projection (fp16x2 pipelined) -> Q,K bf16 hi/lo; V single fp16
    gemm_h2<<<dim3(QKVLD / 128, M / 128), 256, 73728>>>(
        xh, xl, wqh, bqkv, nullptr, qh, ql, M, QKVLD, D_, 1);

    // Causal flash attention (QK bf16x3, PV fp16x2, double-buffered)
    flash_attn_mma<<<dim3(S_ / 128, H_, B_), 256, 49152>>>(qh, ql, ah, al);

    // Output projection (fp16x2 pipelined) -> fp32 out
    gemm_h2<<<dim3(D_ / 128, M / 128), 256, 73728>>>(
        ah, al, wph, bp, out, nullptr, nullptr, M, D_, D_, 0);
}